// round 1
// baseline (speedup 1.0000x reference)
#include <cuda_runtime.h>

#define DD    128
#define MATN  16384          // 128*128
#define BSZ   32
#define SEQ   256
#define CHUNK 16
#define NCH   16             // SEQ / CHUNK
#define PST   128            // Ps smem stride (col-major: Ps[k*PST + row])
#define SMEM_BYTES ((PST*DD + 2*8*DD) * 4)   // 65536 + 8192 = 73728

// Scratch: chunk totals + ping-pong buffer for the Kogge-Stone scan.
__device__ __align__(16) float g_T0[(size_t)BSZ * NCH * MATN];
__device__ __align__(16) float g_T1[(size_t)BSZ * NCH * MATN];

// Load a 128x128 row-major global matrix into SMEM column-major (Ps[k*PST+row]).
// Optionally mirror the untouched row-major copy to `mirror` (coalesced).
__device__ __forceinline__ void load_left(float* Ps, const float* __restrict__ G,
                                          float* __restrict__ mirror, int tid) {
    for (int o = tid << 2; o < MATN; o += 1024) {
        float4 v = *(const float4*)(G + o);
        if (mirror) *(float4*)(mirror + o) = v;
        int row = o >> 7, col = o & 127;
        Ps[(col + 0) * PST + row] = v.x;
        Ps[(col + 1) * PST + row] = v.y;
        Ps[(col + 2) * PST + row] = v.z;
        Ps[(col + 3) * PST + row] = v.w;
    }
    __syncthreads();
}

// CTA-wide 128x128x128 fp32 matmul:  C = Ps(@smem, col-major) @ Bg(global, row-major).
// Streams Bg in 8x128 k-tiles through a double-buffered SMEM staging area.
// Optionally writes C back into Ps (for the running prefix product) and to up to
// two global row-major destinations.
__device__ __forceinline__ void cta_mm(float* Ps, float* Bs,
                                       const float* __restrict__ Bg,
                                       float* __restrict__ gout1,
                                       float* __restrict__ gout2,
                                       bool writePs, int tid) {
    const int tx = tid & 15, ty = tid >> 4;
    const int r0 = ty << 3, c0 = tx << 3;

    float acc[8][8];
#pragma unroll
    for (int i = 0; i < 8; i++)
#pragma unroll
        for (int j = 0; j < 8; j++) acc[i][j] = 0.f;

    // preload tile 0 (tiles are full-width rows -> contiguous 1024 floats)
    float4 ld = *(const float4*)(Bg + (tid << 2));
    *(float4*)(Bs + (tid << 2)) = ld;
    __syncthreads();

#pragma unroll 1
    for (int kt = 0; kt < 16; kt++) {
        float4 nxt;
        if (kt < 15) nxt = *(const float4*)(Bg + ((size_t)(kt + 1) << 10) + (tid << 2));
        const float* Bc = Bs + ((kt & 1) << 10);
        const float* Pk = Ps + (kt << 3) * PST;
#pragma unroll
        for (int kk = 0; kk < 8; kk++) {
            float4 a0 = *(const float4*)(Pk + kk * PST + r0);
            float4 a1 = *(const float4*)(Pk + kk * PST + r0 + 4);
            float4 b0 = *(const float4*)(Bc + (kk << 7) + c0);
            float4 b1 = *(const float4*)(Bc + (kk << 7) + c0 + 4);
            float av[8], bv[8];
            av[0] = a0.x; av[1] = a0.y; av[2] = a0.z; av[3] = a0.w;
            av[4] = a1.x; av[5] = a1.y; av[6] = a1.z; av[7] = a1.w;
            bv[0] = b0.x; bv[1] = b0.y; bv[2] = b0.z; bv[3] = b0.w;
            bv[4] = b1.x; bv[5] = b1.y; bv[6] = b1.z; bv[7] = b1.w;
#pragma unroll
            for (int i = 0; i < 8; i++)
#pragma unroll
                for (int j = 0; j < 8; j++)
                    acc[i][j] = fmaf(av[i], bv[j], acc[i][j]);
        }
        if (kt < 15) {
            *(float4*)(Bs + (((kt + 1) & 1) << 10) + (tid << 2)) = nxt;
            __syncthreads();
        }
    }

    if (writePs) {
        __syncthreads();  // all Ps reads complete before overwrite
#pragma unroll
        for (int j = 0; j < 8; j++)
#pragma unroll
            for (int i = 0; i < 8; i += 4)
                *(float4*)(Ps + (c0 + j) * PST + r0 + i) =
                    make_float4(acc[i][j], acc[i + 1][j], acc[i + 2][j], acc[i + 3][j]);
        // next cta_mm's first __syncthreads() orders these writes before reads
    }
    if (gout1) {
#pragma unroll
        for (int i = 0; i < 8; i++) {
            *(float4*)(gout1 + ((r0 + i) << 7) + c0) =
                make_float4(acc[i][0], acc[i][1], acc[i][2], acc[i][3]);
            *(float4*)(gout1 + ((r0 + i) << 7) + c0 + 4) =
                make_float4(acc[i][4], acc[i][5], acc[i][6], acc[i][7]);
        }
    }
    if (gout2) {
#pragma unroll
        for (int i = 0; i < 8; i++) {
            *(float4*)(gout2 + ((r0 + i) << 7) + c0) =
                make_float4(acc[i][0], acc[i][1], acc[i][2], acc[i][3]);
            *(float4*)(gout2 + ((r0 + i) << 7) + c0 + 4) =
                make_float4(acc[i][4], acc[i][5], acc[i][6], acc[i][7]);
        }
    }
}

// Phase 1: 512 CTAs = (batch, chunk). Sequential local prefix products inside
// the chunk; running product lives in SMEM. Writes local prefixes to ao,
// chunk total to g_T0.
__global__ void __launch_bounds__(256) k_phase1(const float* __restrict__ in,
                                                float* __restrict__ ao) {
    extern __shared__ float sm[];
    float* Ps = sm;
    float* Bs = sm + PST * DD;
    int b = blockIdx.x >> 4, c = blockIdx.x & 15;
    int tid = threadIdx.x;
    const float* A0 = in + (size_t)(b * SEQ + c * CHUNK) * MATN;
    float* out0 = ao + (size_t)(b * SEQ + c * CHUNK) * MATN;

    load_left(Ps, A0, out0, tid);  // local prefix for s=0 is A0 itself
    for (int s = 1; s < CHUNK; s++) {
        float* g2 = (s == CHUNK - 1) ? (g_T0 + (size_t)(b * NCH + c) * MATN) : nullptr;
        cta_mm(Ps, Bs, A0 + (size_t)s * MATN, out0 + (size_t)s * MATN, g2, true, tid);
    }
}

// Phase 2: one Kogge-Stone level over the 16 chunk totals (per batch).
// dst[c] = src[c-d] @ src[c] for c>=d (earlier segment on the LEFT), else copy.
__global__ void __launch_bounds__(256) k_scan(int dlev, int dir) {
    float* src = dir ? g_T1 : g_T0;
    float* dst = dir ? g_T0 : g_T1;
    int b = blockIdx.x >> 4, c = blockIdx.x & 15;
    int tid = threadIdx.x;
    size_t idx = (size_t)(b * NCH + c) * MATN;
    if (c < dlev) {
        for (int o = tid << 2; o < MATN; o += 1024)
            *(float4*)(dst + idx + o) = *(const float4*)(src + idx + o);
        return;
    }
    extern __shared__ float sm[];
    float* Ps = sm;
    float* Bs = sm + PST * DD;
    load_left(Ps, src + (size_t)(b * NCH + (c - dlev)) * MATN, nullptr, tid);
    cta_mm(Ps, Bs, src + idx, dst + idx, nullptr, false, tid);
}

// Phase 3: for chunks 1..15, out[t] = S[chunk-1] @ local[t]. Left operand loaded
// to SMEM once, amortized over 8 matmuls per CTA. grid = 32 * 15 * 2.
__global__ void __launch_bounds__(256) k_apply(float* __restrict__ ao) {
    extern __shared__ float sm[];
    float* Ps = sm;
    float* Bs = sm + PST * DD;
    int tid = threadIdx.x;
    int blk = blockIdx.x;
    int b = blk / 30;
    int rem = blk % 30;
    int c = (rem >> 1) + 1;   // chunk 1..15
    int g = rem & 1;          // half of the chunk
    load_left(Ps, g_T0 + (size_t)(b * NCH + (c - 1)) * MATN, nullptr, tid);
    int t0 = c * CHUNK + g * 8;
    for (int u = 0; u < 8; u++) {
        float* L = ao + (size_t)(b * SEQ + t0 + u) * MATN;
        // reads of L complete (into SMEM) before any STG of the result
        cta_mm(Ps, Bs, L, L, nullptr, false, tid);
    }
}

// Phase 4: x[b] = all_outputs[b][255]
__global__ void __launch_bounds__(256) k_xcopy(const float* __restrict__ ao,
                                               float* __restrict__ x) {
    int b = blockIdx.x, tid = threadIdx.x;
    const float* s = ao + (size_t)(b * SEQ + (SEQ - 1)) * MATN;
    float* d = x + (size_t)b * MATN;
    for (int o = tid << 2; o < MATN; o += 1024)
        *(float4*)(d + o) = *(const float4*)(s + o);
}

extern "C" void kernel_launch(void* const* d_in, const int* in_sizes, int n_in,
                              void* d_out, int out_size) {
    const float* in = (const float*)d_in[0];
    float* out = (float*)d_out;
    const size_t AO = (size_t)BSZ * SEQ * MATN;   // all_outputs elems
    const size_t XN = (size_t)BSZ * MATN;         // x elems

    // Tuple (x, all_outputs) flattened in order: x first, then all_outputs.
    float* x = nullptr;
    float* ao = out;
    if ((size_t)out_size >= AO + XN) { x = out; ao = out + XN; }

    cudaFuncSetAttribute(k_phase1, cudaFuncAttributeMaxDynamicSharedMemorySize, SMEM_BYTES);
    cudaFuncSetAttribute(k_scan,   cudaFuncAttributeMaxDynamicSharedMemorySize, SMEM_BYTES);
    cudaFuncSetAttribute(k_apply,  cudaFuncAttributeMaxDynamicSharedMemorySize, SMEM_BYTES);

    k_phase1<<<BSZ * NCH, 256, SMEM_BYTES>>>(in, ao);
    k_scan<<<BSZ * NCH, 256, SMEM_BYTES>>>(1, 0);   // T0 -> T1
    k_scan<<<BSZ * NCH, 256, SMEM_BYTES>>>(2, 1);   // T1 -> T0
    k_scan<<<BSZ * NCH, 256, SMEM_BYTES>>>(4, 0);   // T0 -> T1
    k_scan<<<BSZ * NCH, 256, SMEM_BYTES>>>(8, 1);   // T1 -> T0 (inclusive scan final)
    k_apply<<<BSZ * 15 * 2, 256, SMEM_BYTES>>>(ao);
    if (x) k_xcopy<<<BSZ, 256>>>(ao, x);
}

// round 3
// speedup vs baseline: 1.0229x; 1.0229x over previous
#include <cuda_runtime.h>

#define DD    128
#define MATN  16384          // 128*128
#define BSZ   32
#define SEQ   256
#define CHUNK 16
#define NCH   16             // SEQ / CHUNK
#define PST   128            // Ps smem stride (col-major: Ps[k*PST + row])
#define SMEM_BYTES ((PST*DD + 2*8*DD) * 4)   // 65536 + 8192 = 73728

typedef unsigned long long u64;

// Scratch: chunk totals + ping-pong buffer for the Kogge-Stone scan.
__device__ __align__(16) float g_T0[(size_t)BSZ * NCH * MATN];
__device__ __align__(16) float g_T1[(size_t)BSZ * NCH * MATN];

// Packed f32x2 helpers (Blackwell sm_10x)
__device__ __forceinline__ void ffma2(u64& d, u64 a, u64 b) {
    asm("fma.rn.f32x2 %0, %1, %2, %0;" : "+l"(d) : "l"(a), "l"(b));
}
__device__ __forceinline__ u64 dup2(float x) {
    u64 r;
    asm("mov.b64 %0, {%1, %1};" : "=l"(r) : "f"(x));
    return r;
}
__device__ __forceinline__ float2 unpk(u64 p) {
    float2 f;
    asm("mov.b64 {%0, %1}, %2;" : "=f"(f.x), "=f"(f.y) : "l"(p));
    return f;
}

// Load a 128x128 row-major global matrix into SMEM column-major (Ps[k*PST+row]).
// Optionally mirror the untouched row-major copy to `mirror` (coalesced).
__device__ __forceinline__ void load_left(float* Ps, const float* __restrict__ G,
                                          float* __restrict__ mirror, int tid) {
    for (int o = tid << 2; o < MATN; o += 1024) {
        float4 v = *(const float4*)(G + o);
        if (mirror) *(float4*)(mirror + o) = v;
        int row = o >> 7, col = o & 127;
        Ps[(col + 0) * PST + row] = v.x;
        Ps[(col + 1) * PST + row] = v.y;
        Ps[(col + 2) * PST + row] = v.z;
        Ps[(col + 3) * PST + row] = v.w;
    }
    __syncthreads();
}

// CTA-wide 128x128x128 fp32 matmul:  C = Ps(@smem, col-major) @ Bg(global, row-major).
// Packed f32x2 FMA micro-kernel: 4x8 accumulators of row-pairs.
// Streams Bg in 8x128 k-tiles through a double-buffered SMEM staging area.
__device__ __forceinline__ void cta_mm(float* Ps, float* Bs,
                                       const float* __restrict__ Bg,
                                       float* __restrict__ gout1,
                                       float* __restrict__ gout2,
                                       bool writePs, int tid) {
    const int tx = tid & 15, ty = tid >> 4;
    const int r0 = ty << 3, c0 = tx << 3;

    u64 acc[4][8];
#pragma unroll
    for (int u = 0; u < 4; u++)
#pragma unroll
        for (int j = 0; j < 8; j++) acc[u][j] = 0ull;

    // preload tile 0 (tiles are full-width rows -> contiguous 1024 floats)
    float4 ld = *(const float4*)(Bg + (tid << 2));
    *(float4*)(Bs + (tid << 2)) = ld;
    __syncthreads();

#pragma unroll 1
    for (int kt = 0; kt < 16; kt++) {
        float4 nxt;
        if (kt < 15) nxt = *(const float4*)(Bg + ((size_t)(kt + 1) << 10) + (tid << 2));
        const float* Bc = Bs + ((kt & 1) << 10);
        const float* Pk = Ps + (kt << 3) * PST;
#pragma unroll
        for (int kk = 0; kk < 8; kk++) {
            // A column slice rows r0..r0+7: packed row-pairs for free
            ulonglong2 pa01 = *(const ulonglong2*)(Pk + kk * PST + r0);
            ulonglong2 pa23 = *(const ulonglong2*)(Pk + kk * PST + r0 + 4);
            u64 pa[4];
            pa[0] = pa01.x; pa[1] = pa01.y; pa[2] = pa23.x; pa[3] = pa23.y;
            float4 b0 = *(const float4*)(Bc + (kk << 7) + c0);
            float4 b1 = *(const float4*)(Bc + (kk << 7) + c0 + 4);
            u64 pb[8];
            pb[0] = dup2(b0.x); pb[1] = dup2(b0.y); pb[2] = dup2(b0.z); pb[3] = dup2(b0.w);
            pb[4] = dup2(b1.x); pb[5] = dup2(b1.y); pb[6] = dup2(b1.z); pb[7] = dup2(b1.w);
#pragma unroll
            for (int u = 0; u < 4; u++)
#pragma unroll
                for (int j = 0; j < 8; j++)
                    ffma2(acc[u][j], pa[u], pb[j]);
        }
        if (kt < 15) {
            *(float4*)(Bs + (((kt + 1) & 1) << 10) + (tid << 2)) = nxt;
            __syncthreads();
        }
    }

    if (writePs) {
        __syncthreads();  // all Ps reads complete before overwrite
#pragma unroll
        for (int j = 0; j < 8; j++) {
            // col-major store: row pairs are already packed
            ulonglong2 v0; v0.x = acc[0][j]; v0.y = acc[1][j];
            ulonglong2 v1; v1.x = acc[2][j]; v1.y = acc[3][j];
            *(ulonglong2*)(Ps + (c0 + j) * PST + r0)     = v0;
            *(ulonglong2*)(Ps + (c0 + j) * PST + r0 + 4) = v1;
        }
        // next cta_mm's first __syncthreads() orders these writes before reads
    }
    if (gout1 || gout2) {
#pragma unroll
        for (int u = 0; u < 4; u++) {
            float2 t[8];
#pragma unroll
            for (int j = 0; j < 8; j++) t[j] = unpk(acc[u][j]);
            float4 rA0 = make_float4(t[0].x, t[1].x, t[2].x, t[3].x);
            float4 rA1 = make_float4(t[4].x, t[5].x, t[6].x, t[7].x);
            float4 rB0 = make_float4(t[0].y, t[1].y, t[2].y, t[3].y);
            float4 rB1 = make_float4(t[4].y, t[5].y, t[6].y, t[7].y);
            int ra = r0 + 2 * u, rb = ra + 1;
            if (gout1) {
                *(float4*)(gout1 + (ra << 7) + c0)     = rA0;
                *(float4*)(gout1 + (ra << 7) + c0 + 4) = rA1;
                *(float4*)(gout1 + (rb << 7) + c0)     = rB0;
                *(float4*)(gout1 + (rb << 7) + c0 + 4) = rB1;
            }
            if (gout2) {
                *(float4*)(gout2 + (ra << 7) + c0)     = rA0;
                *(float4*)(gout2 + (ra << 7) + c0 + 4) = rA1;
                *(float4*)(gout2 + (rb << 7) + c0)     = rB0;
                *(float4*)(gout2 + (rb << 7) + c0 + 4) = rB1;
            }
        }
    }
}

// Phase 1: 512 CTAs = (batch, chunk). Sequential local prefix products inside
// the chunk; running product lives in SMEM. Writes local prefixes to ao,
// chunk total to g_T0.
__global__ void __launch_bounds__(256) k_phase1(const float* __restrict__ in,
                                                float* __restrict__ ao) {
    extern __shared__ float sm[];
    float* Ps = sm;
    float* Bs = sm + PST * DD;
    int b = blockIdx.x >> 4, c = blockIdx.x & 15;
    int tid = threadIdx.x;
    const float* A0 = in + (size_t)(b * SEQ + c * CHUNK) * MATN;
    float* out0 = ao + (size_t)(b * SEQ + c * CHUNK) * MATN;

    load_left(Ps, A0, out0, tid);  // local prefix for s=0 is A0 itself
    for (int s = 1; s < CHUNK; s++) {
        float* g2 = (s == CHUNK - 1) ? (g_T0 + (size_t)(b * NCH + c) * MATN) : nullptr;
        cta_mm(Ps, Bs, A0 + (size_t)s * MATN, out0 + (size_t)s * MATN, g2, true, tid);
    }
}

// Phase 2: one Kogge-Stone level over the 16 chunk totals (per batch).
// dst[c] = src[c-d] @ src[c] for c>=d (earlier segment on the LEFT), else copy.
__global__ void __launch_bounds__(256) k_scan(int dlev, int dir) {
    float* src = dir ? g_T1 : g_T0;
    float* dst = dir ? g_T0 : g_T1;
    int b = blockIdx.x >> 4, c = blockIdx.x & 15;
    int tid = threadIdx.x;
    size_t idx = (size_t)(b * NCH + c) * MATN;
    if (c < dlev) {
        for (int o = tid << 2; o < MATN; o += 1024)
            *(float4*)(dst + idx + o) = *(const float4*)(src + idx + o);
        return;
    }
    extern __shared__ float sm[];
    float* Ps = sm;
    float* Bs = sm + PST * DD;
    load_left(Ps, src + (size_t)(b * NCH + (c - dlev)) * MATN, nullptr, tid);
    cta_mm(Ps, Bs, src + idx, dst + idx, nullptr, false, tid);
}

// Phase 3: for chunks 1..15, out[t] = S[chunk-1] @ local[t]. Left operand loaded
// to SMEM once, amortized over 4 matmuls per CTA. grid = 32 * 15 * 4.
__global__ void __launch_bounds__(256) k_apply(float* __restrict__ ao) {
    extern __shared__ float sm[];
    float* Ps = sm;
    float* Bs = sm + PST * DD;
    int tid = threadIdx.x;
    int blk = blockIdx.x;
    int b = blk / 60;
    int rem = blk % 60;
    int c = (rem >> 2) + 1;   // chunk 1..15
    int q = rem & 3;          // quarter of the chunk
    load_left(Ps, g_T0 + (size_t)(b * NCH + (c - 1)) * MATN, nullptr, tid);
    int t0 = c * CHUNK + q * 4;
    for (int u = 0; u < 4; u++) {
        float* L = ao + (size_t)(b * SEQ + t0 + u) * MATN;
        // reads of L complete (into SMEM) before any STG of the result
        cta_mm(Ps, Bs, L, L, nullptr, false, tid);
    }
}

// Phase 4: x[b] = all_outputs[b][255]
__global__ void __launch_bounds__(256) k_xcopy(const float* __restrict__ ao,
                                               float* __restrict__ x) {
    int b = blockIdx.x, tid = threadIdx.x;
    const float* s = ao + (size_t)(b * SEQ + (SEQ - 1)) * MATN;
    float* d = x + (size_t)b * MATN;
    for (int o = tid << 2; o < MATN; o += 1024)
        *(float4*)(d + o) = *(const float4*)(s + o);
}

extern "C" void kernel_launch(void* const* d_in, const int* in_sizes, int n_in,
                              void* d_out, int out_size) {
    const float* in = (const float*)d_in[0];
    float* out = (float*)d_out;
    const size_t AO = (size_t)BSZ * SEQ * MATN;   // all_outputs elems
    const size_t XN = (size_t)BSZ * MATN;         // x elems

    // Tuple (x, all_outputs) flattened in order: x first, then all_outputs.
    float* x = nullptr;
    float* ao = out;
    if ((size_t)out_size >= AO + XN) { x = out; ao = out + XN; }

    cudaFuncSetAttribute(k_phase1, cudaFuncAttributeMaxDynamicSharedMemorySize, SMEM_BYTES);
    cudaFuncSetAttribute(k_scan,   cudaFuncAttributeMaxDynamicSharedMemorySize, SMEM_BYTES);
    cudaFuncSetAttribute(k_apply,  cudaFuncAttributeMaxDynamicSharedMemorySize, SMEM_BYTES);

    k_phase1<<<BSZ * NCH, 256, SMEM_BYTES>>>(in, ao);
    k_scan<<<BSZ * NCH, 256, SMEM_BYTES>>>(1, 0);   // T0 -> T1
    k_scan<<<BSZ * NCH, 256, SMEM_BYTES>>>(2, 1);   // T1 -> T0
    k_scan<<<BSZ * NCH, 256, SMEM_BYTES>>>(4, 0);   // T0 -> T1
    k_scan<<<BSZ * NCH, 256, SMEM_BYTES>>>(8, 1);   // T1 -> T0 (inclusive scan final)
    k_apply<<<BSZ * 15 * 4, 256, SMEM_BYTES>>>(ao);
    if (x) k_xcopy<<<BSZ, 256>>>(ao, x);
}

// round 5
// speedup vs baseline: 1.6696x; 1.6322x over previous
#include <cuda_runtime.h>
#include <cuda_bf16.h>
#include <cstdint>

#define DD    128
#define MATN  16384
#define BSZ   32
#define SEQ   256
#define CHUNK 16
#define NCH   16

#define STRB  272                 // smem row stride bytes (17*16 -> conflict-free ldmatrix)
#define TERM  (128 * STRB)        // one 128x128 bf16 term tile: 34816 B
#define OFF_AH 0
#define OFF_AM TERM
#define OFF_BH (2 * TERM)
#define OFF_BM (3 * TERM)
#define SMEM_TOTAL (4 * TERM)     // 139264 B

__device__ __align__(16) float g_T0[(size_t)BSZ * NCH * MATN];
__device__ __align__(16) float g_T1[(size_t)BSZ * NCH * MATN];

// ---------------- PTX helpers ----------------
__device__ __forceinline__ uint32_t smem_u32(const void* p) {
    uint32_t a;
    asm("{ .reg .u64 t; cvta.to.shared.u64 t, %1; cvt.u32.u64 %0, t; }" : "=r"(a) : "l"(p));
    return a;
}
__device__ __forceinline__ void ldsm4(uint32_t* r, uint32_t a) {
    asm volatile("ldmatrix.sync.aligned.m8n8.x4.shared.b16 {%0,%1,%2,%3}, [%4];"
                 : "=r"(r[0]), "=r"(r[1]), "=r"(r[2]), "=r"(r[3]) : "r"(a));
}
__device__ __forceinline__ void ldsm2t(uint32_t* r, uint32_t a) {
    asm volatile("ldmatrix.sync.aligned.m8n8.x2.trans.shared.b16 {%0,%1}, [%2];"
                 : "=r"(r[0]), "=r"(r[1]) : "r"(a));
}
__device__ __forceinline__ void mma16816(float* c, const uint32_t* a, const uint32_t* b) {
    asm volatile(
        "mma.sync.aligned.m16n8k16.row.col.f32.bf16.bf16.f32 "
        "{%0,%1,%2,%3}, {%4,%5,%6,%7}, {%8,%9}, {%0,%1,%2,%3};"
        : "+f"(c[0]), "+f"(c[1]), "+f"(c[2]), "+f"(c[3])
        : "r"(a[0]), "r"(a[1]), "r"(a[2]), "r"(a[3]), "r"(b[0]), "r"(b[1]));
}

// split fp32 -> (h, m) bf16 pair
__device__ __forceinline__ void split1(float f, unsigned short& h, unsigned short& m) {
    __nv_bfloat16 bh = __float2bfloat16(f);
    float r = f - __bfloat162float(bh);
    __nv_bfloat16 bm = __float2bfloat16(r);
    h = __bfloat16_as_ushort(bh);
    m = __bfloat16_as_ushort(bm);
}
__device__ __forceinline__ void split4(float4 v, uint2& H, uint2& M) {
    unsigned short h[4], m[4];
    split1(v.x, h[0], m[0]); split1(v.y, h[1], m[1]);
    split1(v.z, h[2], m[2]); split1(v.w, h[3], m[3]);
    H.x = h[0] | ((uint32_t)h[1] << 16);  H.y = h[2] | ((uint32_t)h[3] << 16);
    M.x = m[0] | ((uint32_t)m[1] << 16);  M.y = m[2] | ((uint32_t)m[3] << 16);
}

// Split a global fp32 128x128 row-major matrix into SMEM term tiles at offH/offM.
// Optionally mirror the fp32 matrix to `mirror` (coalesced copy).
__device__ __forceinline__ void split_to(const float* __restrict__ G,
                                         float* __restrict__ mirror,
                                         char* sm, int offH, int offM, int tid) {
#pragma unroll 4
    for (int it = 0; it < 16; it++) {
        int o = (tid << 2) + (it << 10);
        float4 v = *(const float4*)(G + o);
        if (mirror) *(float4*)(mirror + o) = v;
        uint2 H, M; split4(v, H, M);
        int row = o >> 7, col = o & 127;
        int off = row * STRB + (col << 1);
        *(uint2*)(sm + offH + off) = H;
        *(uint2*)(sm + offM + off) = M;
    }
}

// 128x128x128 matmul on tensor cores: C = A(Ah+Am, smem) @ B(Bh+Bm, smem),
// 3-product bf16 split, fp32 accum in registers.
// Then: write C to g1 (and g2), optionally re-split C into the A term tiles.
__device__ __forceinline__ void cta_mm(char* sm, uint32_t smb,
                                       float* __restrict__ g1,
                                       float* __restrict__ g2,
                                       bool resplitA, int tid) {
    const int lane = tid & 31, w = tid >> 5;
    const int mb = (w >> 2) << 6;   // 0 / 64
    const int nb = (w & 3) << 5;    // 0 / 32 / 64 / 96

    float acc[4][4][4];
#pragma unroll
    for (int mt = 0; mt < 4; mt++)
#pragma unroll
        for (int nt = 0; nt < 4; nt++)
#pragma unroll
            for (int i = 0; i < 4; i++) acc[mt][nt][i] = 0.f;

    const uint32_t a_lane = (uint32_t)((lane & 15) * STRB + ((lane >> 4) << 4));
    const uint32_t b_lane = (uint32_t)((lane & 15) * STRB);

#pragma unroll 1
    for (int k0 = 0; k0 < 8; k0++) {
        const int kk = k0 << 4;
        uint32_t ah[4][4], am[4][4];
#pragma unroll
        for (int mt = 0; mt < 4; mt++) {
            uint32_t base = smb + (uint32_t)((mb + mt * 16) * STRB + (kk << 1)) + a_lane;
            ldsm4(ah[mt], base + OFF_AH);
            ldsm4(am[mt], base + OFF_AM);
        }
        uint32_t bh[4][2], bm[4][2];
#pragma unroll
        for (int nt = 0; nt < 4; nt++) {
            uint32_t base = smb + (uint32_t)(kk * STRB + ((nb + nt * 8) << 1)) + b_lane;
            ldsm2t(bh[nt], base + OFF_BH);
            ldsm2t(bm[nt], base + OFF_BM);
        }
#pragma unroll
        for (int mt = 0; mt < 4; mt++)
#pragma unroll
            for (int nt = 0; nt < 4; nt++) {
                mma16816(acc[mt][nt], ah[mt], bh[nt]);
                mma16816(acc[mt][nt], ah[mt], bm[nt]);
                mma16816(acc[mt][nt], am[mt], bh[nt]);
            }
    }

    __syncthreads();   // all A/B smem reads done before any resplit overwrite

    const int r_off = lane >> 2;
    const int c_off = (lane & 3) << 1;
#pragma unroll
    for (int mt = 0; mt < 4; mt++) {
#pragma unroll
        for (int nt = 0; nt < 4; nt++) {
            int row0 = mb + mt * 16 + r_off;
            int col  = nb + nt * 8 + c_off;
#pragma unroll
            for (int half = 0; half < 2; half++) {
                int row = row0 + half * 8;
                float vx = acc[mt][nt][2 * half];
                float vy = acc[mt][nt][2 * half + 1];
                if (g1) *(float2*)(g1 + ((size_t)row << 7) + col) = make_float2(vx, vy);
                if (g2) *(float2*)(g2 + ((size_t)row << 7) + col) = make_float2(vx, vy);
                if (resplitA) {
                    unsigned short h0, m0, h1, m1;
                    split1(vx, h0, m0);
                    split1(vy, h1, m1);
                    int off = row * STRB + (col << 1);
                    *(uint32_t*)(sm + OFF_AH + off) = h0 | ((uint32_t)h1 << 16);
                    *(uint32_t*)(sm + OFF_AM + off) = m0 | ((uint32_t)m1 << 16);
                }
            }
        }
    }
    __syncthreads();   // resplit visible before next step's compute
}

// one full step: split B from global, compute, epilogue
__device__ __forceinline__ void mm_step(const float* __restrict__ Bg,
                                        float* __restrict__ g1, float* __restrict__ g2,
                                        bool resplitA, char* sm, uint32_t smb, int tid) {
    split_to(Bg, nullptr, sm, OFF_BH, OFF_BM, tid);
    __syncthreads();
    cta_mm(sm, smb, g1, g2, resplitA, tid);
}

// ---------------- kernels ----------------

__global__ void __launch_bounds__(256, 1) k_phase1(const float* __restrict__ in,
                                                   float* __restrict__ ao) {
    extern __shared__ char sm[];
    uint32_t smb = smem_u32(sm);
    int tid = threadIdx.x;
    int b = blockIdx.x >> 4, c = blockIdx.x & 15;
    const float* A0 = in + (size_t)(b * SEQ + c * CHUNK) * MATN;
    float* out0 = ao + (size_t)(b * SEQ + c * CHUNK) * MATN;

    split_to(A0, out0, sm, OFF_AH, OFF_AM, tid);   // prefix[0] = A0, mirrored out
    for (int s = 1; s < CHUNK; s++) {
        bool last = (s == CHUNK - 1);
        mm_step(A0 + (size_t)s * MATN, out0 + (size_t)s * MATN,
                last ? (g_T0 + (size_t)(b * NCH + c) * MATN) : nullptr,
                !last, sm, smb, tid);
    }
}

__global__ void __launch_bounds__(256, 1) k_scan(int dlev, int dir) {
    float* src = dir ? g_T1 : g_T0;
    float* dst = dir ? g_T0 : g_T1;
    int b = blockIdx.x >> 4, c = blockIdx.x & 15;
    int tid = threadIdx.x;
    size_t idx = (size_t)(b * NCH + c) * MATN;
    if (c < dlev) {
        for (int o = tid << 2; o < MATN; o += 1024)
            *(float4*)(dst + idx + o) = *(const float4*)(src + idx + o);
        return;
    }
    extern __shared__ char sm[];
    uint32_t smb = smem_u32(sm);
    split_to(src + (size_t)(b * NCH + (c - dlev)) * MATN, nullptr, sm, OFF_AH, OFF_AM, tid);
    mm_step(src + idx, dst + idx, nullptr, false, sm, smb, tid);
}

__global__ void __launch_bounds__(256, 1) k_apply(float* __restrict__ ao) {
    extern __shared__ char sm[];
    uint32_t smb = smem_u32(sm);
    int tid = threadIdx.x;
    int blk = blockIdx.x;
    int b = blk / 30;
    int rem = blk % 30;
    int c = (rem >> 1) + 1;   // chunk 1..15
    int g = rem & 1;          // half of the chunk
    split_to(g_T0 + (size_t)(b * NCH + (c - 1)) * MATN, nullptr, sm, OFF_AH, OFF_AM, tid);
    int t0 = c * CHUNK + g * 8;
    for (int u = 0; u < 8; u++) {
        float* L = ao + (size_t)(b * SEQ + t0 + u) * MATN;
        mm_step(L, L, nullptr, false, sm, smb, tid);
    }
}

__global__ void __launch_bounds__(256) k_xcopy(const float* __restrict__ ao,
                                               float* __restrict__ x) {
    int b = blockIdx.x, tid = threadIdx.x;
    const float* s = ao + (size_t)(b * SEQ + (SEQ - 1)) * MATN;
    float* d = x + (size_t)b * MATN;
    for (int o = tid << 2; o < MATN; o += 1024)
        *(float4*)(d + o) = *(const float4*)(s + o);
}

extern "C" void kernel_launch(void* const* d_in, const int* in_sizes, int n_in,
                              void* d_out, int out_size) {
    const float* in = (const float*)d_in[0];
    float* out = (float*)d_out;
    const size_t AO = (size_t)BSZ * SEQ * MATN;
    const size_t XN = (size_t)BSZ * MATN;

    float* x = nullptr;
    float* ao = out;
    if ((size_t)out_size >= AO + XN) { x = out; ao = out + XN; }

    cudaFuncSetAttribute(k_phase1, cudaFuncAttributeMaxDynamicSharedMemorySize, SMEM_TOTAL);
    cudaFuncSetAttribute(k_scan,   cudaFuncAttributeMaxDynamicSharedMemorySize, SMEM_TOTAL);
    cudaFuncSetAttribute(k_apply,  cudaFuncAttributeMaxDynamicSharedMemorySize, SMEM_TOTAL);

    k_phase1<<<BSZ * NCH, 256, SMEM_TOTAL>>>(in, ao);
    k_scan<<<BSZ * NCH, 256, SMEM_TOTAL>>>(1, 0);
    k_scan<<<BSZ * NCH, 256, SMEM_TOTAL>>>(2, 1);
    k_scan<<<BSZ * NCH, 256, SMEM_TOTAL>>>(4, 0);
    k_scan<<<BSZ * NCH, 256, SMEM_TOTAL>>>(8, 1);
    k_apply<<<BSZ * 15 * 2, 256, SMEM_TOTAL>>>(ao);
    if (x) k_xcopy<<<BSZ, 256>>>(ao, x);
}

// round 8
// speedup vs baseline: 1.9559x; 1.1715x over previous
#include <cuda_runtime.h>
#include <cuda_bf16.h>
#include <cstdint>

#define DD    128
#define MATN  16384
#define BSZ   32
#define SEQ   256
#define CHUNK 16
#define NCH   16

#define STRB  272                 // smem row stride bytes (17*16 -> conflict-free ldmatrix)
#define TERM  (128 * STRB)        // one 128x128 bf16 term tile: 34816 B
#define OFF_AH 0
#define OFF_AM TERM
#define OFF_BH (2 * TERM)
#define OFF_BM (3 * TERM)
#define OFF_ST (4 * TERM)         // raw fp32 staging for next B (65536 B)
#define SMEM_TOTAL (4 * TERM + 65536)   // 204800 B

__device__ __align__(16) float g_T0[(size_t)BSZ * NCH * MATN];
__device__ __align__(16) float g_T1[(size_t)BSZ * NCH * MATN];

// ---------------- PTX helpers ----------------
__device__ __forceinline__ uint32_t smem_u32(const void* p) {
    uint32_t a;
    asm("{ .reg .u64 t; cvta.to.shared.u64 t, %1; cvt.u32.u64 %0, t; }" : "=r"(a) : "l"(p));
    return a;
}
__device__ __forceinline__ void ldsm4(uint32_t* r, uint32_t a) {
    asm volatile("ldmatrix.sync.aligned.m8n8.x4.shared.b16 {%0,%1,%2,%3}, [%4];"
                 : "=r"(r[0]), "=r"(r[1]), "=r"(r[2]), "=r"(r[3]) : "r"(a));
}
__device__ __forceinline__ void ldsm2t(uint32_t* r, uint32_t a) {
    asm volatile("ldmatrix.sync.aligned.m8n8.x2.trans.shared.b16 {%0,%1}, [%2];"
                 : "=r"(r[0]), "=r"(r[1]) : "r"(a));
}
__device__ __forceinline__ void mma16816(float* c, const uint32_t* a, const uint32_t* b) {
    asm volatile(
        "mma.sync.aligned.m16n8k16.row.col.f32.bf16.bf16.f32 "
        "{%0,%1,%2,%3}, {%4,%5,%6,%7}, {%8,%9}, {%0,%1,%2,%3};"
        : "+f"(c[0]), "+f"(c[1]), "+f"(c[2]), "+f"(c[3])
        : "r"(a[0]), "r"(a[1]), "r"(a[2]), "r"(a[3]), "r"(b[0]), "r"(b[1]));
}
__device__ __forceinline__ void cpasync16(uint32_t dst, const void* src) {
    asm volatile("cp.async.cg.shared.global [%0], [%1], 16;" :: "r"(dst), "l"(src) : "memory");
}
__device__ __forceinline__ void cp_commit() { asm volatile("cp.async.commit_group;" ::: "memory"); }
__device__ __forceinline__ void cp_wait0()  { asm volatile("cp.async.wait_group 0;"  ::: "memory"); }

// split fp32 -> (h, m) bf16 pair
__device__ __forceinline__ void split1(float f, unsigned short& h, unsigned short& m) {
    __nv_bfloat16 bh = __float2bfloat16(f);
    float r = f - __bfloat162float(bh);
    __nv_bfloat16 bm = __float2bfloat16(r);
    h = __bfloat16_as_ushort(bh);
    m = __bfloat16_as_ushort(bm);
}
__device__ __forceinline__ void split4(float4 v, uint2& H, uint2& M) {
    unsigned short h[4], m[4];
    split1(v.x, h[0], m[0]); split1(v.y, h[1], m[1]);
    split1(v.z, h[2], m[2]); split1(v.w, h[3], m[3]);
    H.x = h[0] | ((uint32_t)h[1] << 16);  H.y = h[2] | ((uint32_t)h[3] << 16);
    M.x = m[0] | ((uint32_t)m[1] << 16);  M.y = m[2] | ((uint32_t)m[3] << 16);
}

// Split a global fp32 128x128 row-major matrix into SMEM term tiles at offH/offM.
// Optionally mirror the fp32 matrix to `mirror` (coalesced copy).
__device__ __forceinline__ void split_to(const float* __restrict__ G,
                                         float* __restrict__ mirror,
                                         char* sm, int offH, int offM, int tid) {
#pragma unroll 4
    for (int it = 0; it < 16; it++) {
        int o = (tid << 2) + (it << 10);
        float4 v = *(const float4*)(G + o);
        if (mirror) *(float4*)(mirror + o) = v;
        uint2 H, M; split4(v, H, M);
        int off = (o >> 7) * STRB + ((o & 127) << 1);
        *(uint2*)(sm + offH + off) = H;
        *(uint2*)(sm + offM + off) = M;
    }
}

// 128x128x128 matmul on tensor cores: C = A(Ah+Am) @ B(Bh+Bm), 3-product bf16
// split, fp32 accum in registers. Pipelined: while computing, cp.async-prefetch
// nextB (raw fp32) into the staging buffer; in the epilogue phase split it into
// the B term tiles for the next step. Also writes C to g1 (and g2) and
// optionally re-splits C into the A term tiles.
__device__ __forceinline__ void cta_mm(char* sm, uint32_t smb,
                                       const float* __restrict__ nextB,
                                       float* __restrict__ g1,
                                       float* __restrict__ g2,
                                       bool resplitA, int tid) {
    const int lane = tid & 31, w = tid >> 5;
    const int mb = (w >> 2) << 6;   // 0 / 64
    const int nb = (w & 3) << 5;    // 0 / 32 / 64 / 96

    // issue async prefetch of next B tile (raw fp32 -> stage)
    if (nextB) {
#pragma unroll
        for (int it = 0; it < 16; it++)
            cpasync16(smb + OFF_ST + (uint32_t)((tid << 4) + (it << 12)),
                      nextB + (tid << 2) + (it << 10));
        cp_commit();
    }

    float acc[4][4][4];
#pragma unroll
    for (int mt = 0; mt < 4; mt++)
#pragma unroll
        for (int nt = 0; nt < 4; nt++)
#pragma unroll
            for (int i = 0; i < 4; i++) acc[mt][nt][i] = 0.f;

    const uint32_t a_lane = (uint32_t)((lane & 15) * STRB + ((lane >> 4) << 4));
    const uint32_t b_lane = (uint32_t)((lane & 15) * STRB);

#pragma unroll 1
    for (int k0 = 0; k0 < 8; k0++) {
        const int kk = k0 << 4;
        uint32_t ah[4][4], am[4][4];
#pragma unroll
        for (int mt = 0; mt < 4; mt++) {
            uint32_t base = smb + (uint32_t)((mb + mt * 16) * STRB + (kk << 1)) + a_lane;
            ldsm4(ah[mt], base + OFF_AH);
            ldsm4(am[mt], base + OFF_AM);
        }
        uint32_t bh[4][2], bm[4][2];
#pragma unroll
        for (int nt = 0; nt < 4; nt++) {
            uint32_t base = smb + (uint32_t)(kk * STRB + ((nb + nt * 8) << 1)) + b_lane;
            ldsm2t(bh[nt], base + OFF_BH);
            ldsm2t(bm[nt], base + OFF_BM);
        }
#pragma unroll
        for (int mt = 0; mt < 4; mt++)
#pragma unroll
            for (int nt = 0; nt < 4; nt++) {
                mma16816(acc[mt][nt], ah[mt], bh[nt]);
                mma16816(acc[mt][nt], ah[mt], bm[nt]);
                mma16816(acc[mt][nt], am[mt], bh[nt]);
            }
    }

    __syncthreads();   // all A/B smem reads done before any overwrite below
    if (nextB) cp_wait0();   // each thread waits for (and will split) its own copies

    const int r_off = lane >> 2;
    const int c_off = (lane & 3) << 1;
#pragma unroll
    for (int mt = 0; mt < 4; mt++) {
#pragma unroll
        for (int nt = 0; nt < 4; nt++) {
            int row0 = mb + mt * 16 + r_off;
            int col  = nb + nt * 8 + c_off;
#pragma unroll
            for (int half = 0; half < 2; half++) {
                int row = row0 + half * 8;
                float vx = acc[mt][nt][2 * half];
                float vy = acc[mt][nt][2 * half + 1];
                if (g1) *(float2*)(g1 + ((size_t)row << 7) + col) = make_float2(vx, vy);
                if (g2) *(float2*)(g2 + ((size_t)row << 7) + col) = make_float2(vx, vy);
                if (resplitA) {
                    unsigned short h0, m0, h1, m1;
                    split1(vx, h0, m0);
                    split1(vy, h1, m1);
                    int off = row * STRB + (col << 1);
                    *(uint32_t*)(sm + OFF_AH + off) = h0 | ((uint32_t)h1 << 16);
                    *(uint32_t*)(sm + OFF_AM + off) = m0 | ((uint32_t)m1 << 16);
                }
            }
        }
    }

    // split the staged next-B tile into the B term buffers (k-loop is done with them)
    if (nextB) {
        const float* st = (const float*)(sm + OFF_ST);
#pragma unroll 4
        for (int it = 0; it < 16; it++) {
            int o = (tid << 2) + (it << 10);
            float4 v = *(const float4*)(st + o);
            uint2 H, M; split4(v, H, M);
            int off = (o >> 7) * STRB + ((o & 127) << 1);
            *(uint2*)(sm + OFF_BH + off) = H;
            *(uint2*)(sm + OFF_BM + off) = M;
        }
    }
    __syncthreads();   // new A/B tiles visible before next step's compute
}

// ---------------- kernels ----------------

__global__ void __launch_bounds__(256, 1) k_phase1(const float* __restrict__ in,
                                                   float* __restrict__ ao) {
    extern __shared__ char sm[];
    uint32_t smb = smem_u32(sm);
    int tid = threadIdx.x;
    int b = blockIdx.x >> 4, c = blockIdx.x & 15;
    const float* A0 = in + (size_t)(b * SEQ + c * CHUNK) * MATN;
    float* out0 = ao + (size_t)(b * SEQ + c * CHUNK) * MATN;

    split_to(A0, out0, sm, OFF_AH, OFF_AM, tid);            // prefix[0] = A0, mirrored out
    split_to(A0 + MATN, nullptr, sm, OFF_BH, OFF_BM, tid);  // first B
    __syncthreads();
    for (int s = 1; s < CHUNK; s++) {
        bool last = (s == CHUNK - 1);
        cta_mm(sm, smb,
               last ? nullptr : (A0 + (size_t)(s + 1) * MATN),
               out0 + (size_t)s * MATN,
               last ? (g_T0 + (size_t)(b * NCH + c) * MATN) : nullptr,
               !last, tid);
    }
}

__global__ void __launch_bounds__(256, 1) k_scan(int dlev, int dir) {
    float* src = dir ? g_T1 : g_T0;
    float* dst = dir ? g_T0 : g_T1;
    int b = blockIdx.x >> 4, c = blockIdx.x & 15;
    int tid = threadIdx.x;
    size_t idx = (size_t)(b * NCH + c) * MATN;
    if (c < dlev) {
        for (int o = tid << 2; o < MATN; o += 1024)
            *(float4*)(dst + idx + o) = *(const float4*)(src + idx + o);
        return;
    }
    extern __shared__ char sm[];
    uint32_t smb = smem_u32(sm);
    split_to(src + (size_t)(b * NCH + (c - dlev)) * MATN, nullptr, sm, OFF_AH, OFF_AM, tid);
    split_to(src + idx, nullptr, sm, OFF_BH, OFF_BM, tid);
    __syncthreads();
    cta_mm(sm, smb, nullptr, dst + idx, nullptr, false, tid);
}

__global__ void __launch_bounds__(256, 1) k_apply(float* __restrict__ ao) {
    extern __shared__ char sm[];
    uint32_t smb = smem_u32(sm);
    int tid = threadIdx.x;
    int blk = blockIdx.x;
    int b = blk / 30;
    int rem = blk % 30;
    int c = (rem >> 1) + 1;   // chunk 1..15
    int g = rem & 1;          // half of the chunk
    int t0 = c * CHUNK + g * 8;
    float* L0 = ao + (size_t)(b * SEQ + t0) * MATN;

    split_to(g_T0 + (size_t)(b * NCH + (c - 1)) * MATN, nullptr, sm, OFF_AH, OFF_AM, tid);
    split_to(L0, nullptr, sm, OFF_BH, OFF_BM, tid);
    __syncthreads();
    for (int u = 0; u < 8; u++) {
        cta_mm(sm, smb,
               (u < 7) ? (L0 + (size_t)(u + 1) * MATN) : nullptr,
               L0 + (size_t)u * MATN, nullptr, false, tid);
    }
}

__global__ void __launch_bounds__(256) k_xcopy(const float* __restrict__ ao,
                                               float* __restrict__ x) {
    int b = blockIdx.x, tid = threadIdx.x;
    const float* s = ao + (size_t)(b * SEQ + (SEQ - 1)) * MATN;
    float* d = x + (size_t)b * MATN;
    for (int o = tid << 2; o < MATN; o += 1024)
        *(float4*)(d + o) = *(const float4*)(s + o);
}

extern "C" void kernel_launch(void* const* d_in, const int* in_sizes, int n_in,
                              void* d_out, int out_size) {
    const float* in = (const float*)d_in[0];
    float* out = (float*)d_out;
    const size_t AO = (size_t)BSZ * SEQ * MATN;
    const size_t XN = (size_t)BSZ * MATN;

    float* x = nullptr;
    float* ao = out;
    if ((size_t)out_size >= AO + XN) { x = out; ao = out + XN; }

    cudaFuncSetAttribute(k_phase1, cudaFuncAttributeMaxDynamicSharedMemorySize, SMEM_TOTAL);
    cudaFuncSetAttribute(k_scan,   cudaFuncAttributeMaxDynamicSharedMemorySize, SMEM_TOTAL);
    cudaFuncSetAttribute(k_apply,  cudaFuncAttributeMaxDynamicSharedMemorySize, SMEM_TOTAL);

    k_phase1<<<BSZ * NCH, 256, SMEM_TOTAL>>>(in, ao);
    k_scan<<<BSZ * NCH, 256, SMEM_TOTAL>>>(1, 0);
    k_scan<<<BSZ * NCH, 256, SMEM_TOTAL>>>(2, 1);
    k_scan<<<BSZ * NCH, 256, SMEM_TOTAL>>>(4, 0);
    k_scan<<<BSZ * NCH, 256, SMEM_TOTAL>>>(8, 1);
    k_apply<<<BSZ * 15 * 2, 256, SMEM_TOTAL>>>(ao);
    if (x) k_xcopy<<<BSZ, 256>>>(ao, x);
}

// round 9
// speedup vs baseline: 2.1979x; 1.1237x over previous
#include <cuda_runtime.h>
#include <cuda_bf16.h>
#include <cstdint>

#define DD    128
#define MATN  16384
#define BSZ   32
#define SEQ   256
#define CHUNK 16
#define NCH   16

#define NT    512                 // threads per CTA (16 warps)
#define STRB  272                 // smem row stride bytes (17*16 -> conflict-free ldmatrix)
#define TERM  (128 * STRB)        // one 128x128 bf16 term tile: 34816 B
#define OFF_AH 0
#define OFF_AM TERM
#define OFF_BH (2 * TERM)
#define OFF_BM (3 * TERM)
#define OFF_ST (4 * TERM)         // raw fp32 staging for next B (65536 B)
#define SMEM_TOTAL (4 * TERM + 65536)   // 204800 B

__device__ __align__(16) float g_T0[(size_t)BSZ * NCH * MATN];
__device__ __align__(16) float g_T1[(size_t)BSZ * NCH * MATN];

// ---------------- PTX helpers ----------------
__device__ __forceinline__ uint32_t smem_u32(const void* p) {
    uint32_t a;
    asm("{ .reg .u64 t; cvta.to.shared.u64 t, %1; cvt.u32.u64 %0, t; }" : "=r"(a) : "l"(p));
    return a;
}
__device__ __forceinline__ void ldsm4(uint32_t* r, uint32_t a) {
    asm volatile("ldmatrix.sync.aligned.m8n8.x4.shared.b16 {%0,%1,%2,%3}, [%4];"
                 : "=r"(r[0]), "=r"(r[1]), "=r"(r[2]), "=r"(r[3]) : "r"(a));
}
__device__ __forceinline__ void ldsm2t(uint32_t* r, uint32_t a) {
    asm volatile("ldmatrix.sync.aligned.m8n8.x2.trans.shared.b16 {%0,%1}, [%2];"
                 : "=r"(r[0]), "=r"(r[1]) : "r"(a));
}
__device__ __forceinline__ void mma16816(float* c, const uint32_t* a, const uint32_t* b) {
    asm volatile(
        "mma.sync.aligned.m16n8k16.row.col.f32.bf16.bf16.f32 "
        "{%0,%1,%2,%3}, {%4,%5,%6,%7}, {%8,%9}, {%0,%1,%2,%3};"
        : "+f"(c[0]), "+f"(c[1]), "+f"(c[2]), "+f"(c[3])
        : "r"(a[0]), "r"(a[1]), "r"(a[2]), "r"(a[3]), "r"(b[0]), "r"(b[1]));
}
__device__ __forceinline__ void cpasync16(uint32_t dst, const void* src) {
    asm volatile("cp.async.cg.shared.global [%0], [%1], 16;" :: "r"(dst), "l"(src) : "memory");
}
__device__ __forceinline__ void cp_commit() { asm volatile("cp.async.commit_group;" ::: "memory"); }
__device__ __forceinline__ void cp_wait0()  { asm volatile("cp.async.wait_group 0;"  ::: "memory"); }

// split fp32 -> (h, m) bf16 pair
__device__ __forceinline__ void split1(float f, unsigned short& h, unsigned short& m) {
    __nv_bfloat16 bh = __float2bfloat16(f);
    float r = f - __bfloat162float(bh);
    __nv_bfloat16 bm = __float2bfloat16(r);
    h = __bfloat16_as_ushort(bh);
    m = __bfloat16_as_ushort(bm);
}
__device__ __forceinline__ void split4(float4 v, uint2& H, uint2& M) {
    unsigned short h[4], m[4];
    split1(v.x, h[0], m[0]); split1(v.y, h[1], m[1]);
    split1(v.z, h[2], m[2]); split1(v.w, h[3], m[3]);
    H.x = h[0] | ((uint32_t)h[1] << 16);  H.y = h[2] | ((uint32_t)h[3] << 16);
    M.x = m[0] | ((uint32_t)m[1] << 16);  M.y = m[2] | ((uint32_t)m[3] << 16);
}

// Split a global fp32 128x128 row-major matrix into SMEM term tiles at offH/offM.
// Optionally mirror the fp32 matrix to `mirror` (coalesced copy). NT=512 threads.
__device__ __forceinline__ void split_to(const float* __restrict__ G,
                                         float* __restrict__ mirror,
                                         char* sm, int offH, int offM, int tid) {
#pragma unroll 4
    for (int it = 0; it < 8; it++) {
        int o = (tid << 2) + (it << 11);
        float4 v = *(const float4*)(G + o);
        if (mirror) *(float4*)(mirror + o) = v;
        uint2 H, M; split4(v, H, M);
        int off = (o >> 7) * STRB + ((o & 127) << 1);
        *(uint2*)(sm + offH + off) = H;
        *(uint2*)(sm + offM + off) = M;
    }
}

// 128x128x128 matmul on tensor cores: C = A(Ah+Am) @ B(Bh+Bm), 3-product bf16
// split, fp32 accum in registers. 16 warps, each owns a 32x32 C tile.
// Fragment-level double buffering: LDSMs for k0+1 issue before k0's MMAs.
// cp.async-prefetches nextB (raw fp32) during compute; splits it in the epilogue.
__device__ __forceinline__ void cta_mm(char* sm, uint32_t smb,
                                       const float* __restrict__ nextB,
                                       float* __restrict__ g1,
                                       float* __restrict__ g2,
                                       bool resplitA, int tid) {
    const int lane = tid & 31, w = tid >> 5;
    const int mb = (w >> 2) << 5;   // 0/32/64/96
    const int nb = (w & 3) << 5;    // 0/32/64/96

    // async prefetch of next B tile (raw fp32 -> stage)
    if (nextB) {
#pragma unroll
        for (int it = 0; it < 8; it++)
            cpasync16(smb + OFF_ST + (uint32_t)((tid << 4) + (it << 13)),
                      nextB + (tid << 2) + (it << 11));
        cp_commit();
    }

    float acc[2][4][4];
#pragma unroll
    for (int mt = 0; mt < 2; mt++)
#pragma unroll
        for (int nt = 0; nt < 4; nt++)
#pragma unroll
            for (int i = 0; i < 4; i++) acc[mt][nt][i] = 0.f;

    const uint32_t a_lane = (uint32_t)((lane & 15) * STRB + ((lane >> 4) << 4));
    const uint32_t b_lane = (uint32_t)((lane & 15) * STRB);

    uint32_t ah[2][2][4], am[2][2][4];   // [buf][mt][reg]
    uint32_t bh[2][4][2], bm[2][4][2];   // [buf][nt][reg]

    // load k0 = 0 fragments into buf 0
#pragma unroll
    for (int mt = 0; mt < 2; mt++) {
        uint32_t base = smb + (uint32_t)((mb + mt * 16) * STRB) + a_lane;
        ldsm4(ah[0][mt], base + OFF_AH);
        ldsm4(am[0][mt], base + OFF_AM);
    }
#pragma unroll
    for (int nt = 0; nt < 4; nt++) {
        uint32_t base = smb + (uint32_t)((nb + nt * 8) << 1) + b_lane;
        ldsm2t(bh[0][nt], base + OFF_BH);
        ldsm2t(bm[0][nt], base + OFF_BM);
    }

#pragma unroll
    for (int k0 = 0; k0 < 8; k0++) {
        const int cur = k0 & 1, nxt = cur ^ 1;
        if (k0 < 7) {   // prefetch k0+1 fragments before consuming k0
            const int kk = (k0 + 1) << 4;
#pragma unroll
            for (int mt = 0; mt < 2; mt++) {
                uint32_t base = smb + (uint32_t)((mb + mt * 16) * STRB + (kk << 1)) + a_lane;
                ldsm4(ah[nxt][mt], base + OFF_AH);
                ldsm4(am[nxt][mt], base + OFF_AM);
            }
#pragma unroll
            for (int nt = 0; nt < 4; nt++) {
                uint32_t base = smb + (uint32_t)(kk * STRB + ((nb + nt * 8) << 1)) + b_lane;
                ldsm2t(bh[nxt][nt], base + OFF_BH);
                ldsm2t(bm[nxt][nt], base + OFF_BM);
            }
        }
#pragma unroll
        for (int mt = 0; mt < 2; mt++)
#pragma unroll
            for (int nt = 0; nt < 4; nt++) {
                mma16816(acc[mt][nt], ah[cur][mt], bh[cur][nt]);
                mma16816(acc[mt][nt], ah[cur][mt], bm[cur][nt]);
                mma16816(acc[mt][nt], am[cur][mt], bh[cur][nt]);
            }
    }

    __syncthreads();   // all A/B smem reads done before any overwrite below
    if (nextB) cp_wait0();   // each thread waits for (and will split) its own copies

    const int r_off = lane >> 2;
    const int c_off = (lane & 3) << 1;
#pragma unroll
    for (int mt = 0; mt < 2; mt++) {
#pragma unroll
        for (int nt = 0; nt < 4; nt++) {
            int row0 = mb + mt * 16 + r_off;
            int col  = nb + nt * 8 + c_off;
#pragma unroll
            for (int half = 0; half < 2; half++) {
                int row = row0 + half * 8;
                float vx = acc[mt][nt][2 * half];
                float vy = acc[mt][nt][2 * half + 1];
                if (g1) *(float2*)(g1 + ((size_t)row << 7) + col) = make_float2(vx, vy);
                if (g2) *(float2*)(g2 + ((size_t)row << 7) + col) = make_float2(vx, vy);
                if (resplitA) {
                    unsigned short h0, m0, h1, m1;
                    split1(vx, h0, m0);
                    split1(vy, h1, m1);
                    int off = row * STRB + (col << 1);
                    *(uint32_t*)(sm + OFF_AH + off) = h0 | ((uint32_t)h1 << 16);
                    *(uint32_t*)(sm + OFF_AM + off) = m0 | ((uint32_t)m1 << 16);
                }
            }
        }
    }

    // split the staged next-B tile into the B term buffers (k-loop is done with them)
    if (nextB) {
        const float* st = (const float*)(sm + OFF_ST);
#pragma unroll 4
        for (int it = 0; it < 8; it++) {
            int o = (tid << 2) + (it << 11);
            float4 v = *(const float4*)(st + o);
            uint2 H, M; split4(v, H, M);
            int off = (o >> 7) * STRB + ((o & 127) << 1);
            *(uint2*)(sm + OFF_BH + off) = H;
            *(uint2*)(sm + OFF_BM + off) = M;
        }
    }
    __syncthreads();   // new A/B tiles visible before next step's compute
}

// ---------------- kernels ----------------

__global__ void __launch_bounds__(NT, 1) k_phase1(const float* __restrict__ in,
                                                  float* __restrict__ ao) {
    extern __shared__ char sm[];
    uint32_t smb = smem_u32(sm);
    int tid = threadIdx.x;
    int b = blockIdx.x >> 4, c = blockIdx.x & 15;
    const float* A0 = in + (size_t)(b * SEQ + c * CHUNK) * MATN;
    float* out0 = ao + (size_t)(b * SEQ + c * CHUNK) * MATN;

    split_to(A0, out0, sm, OFF_AH, OFF_AM, tid);            // prefix[0] = A0, mirrored out
    split_to(A0 + MATN, nullptr, sm, OFF_BH, OFF_BM, tid);  // first B
    __syncthreads();
    for (int s = 1; s < CHUNK; s++) {
        bool last = (s == CHUNK - 1);
        cta_mm(sm, smb,
               last ? nullptr : (A0 + (size_t)(s + 1) * MATN),
               out0 + (size_t)s * MATN,
               last ? (g_T0 + (size_t)(b * NCH + c) * MATN) : nullptr,
               !last, tid);
    }
}

__global__ void __launch_bounds__(NT, 1) k_scan(int dlev, int dir) {
    float* src = dir ? g_T1 : g_T0;
    float* dst = dir ? g_T0 : g_T1;
    int b = blockIdx.x >> 4, c = blockIdx.x & 15;
    int tid = threadIdx.x;
    size_t idx = (size_t)(b * NCH + c) * MATN;
    if (c < dlev) {
        for (int o = tid << 2; o < MATN; o += (NT * 4))
            *(float4*)(dst + idx + o) = *(const float4*)(src + idx + o);
        return;
    }
    extern __shared__ char sm[];
    uint32_t smb = smem_u32(sm);
    split_to(src + (size_t)(b * NCH + (c - dlev)) * MATN, nullptr, sm, OFF_AH, OFF_AM, tid);
    split_to(src + idx, nullptr, sm, OFF_BH, OFF_BM, tid);
    __syncthreads();
    cta_mm(sm, smb, nullptr, dst + idx, nullptr, false, tid);
}

__global__ void __launch_bounds__(NT, 1) k_apply(float* __restrict__ ao) {
    extern __shared__ char sm[];
    uint32_t smb = smem_u32(sm);
    int tid = threadIdx.x;
    int blk = blockIdx.x;
    int b = blk / 30;
    int rem = blk % 30;
    int c = (rem >> 1) + 1;   // chunk 1..15
    int g = rem & 1;          // half of the chunk
    int t0 = c * CHUNK + g * 8;
    float* L0 = ao + (size_t)(b * SEQ + t0) * MATN;

    split_to(g_T0 + (size_t)(b * NCH + (c - 1)) * MATN, nullptr, sm, OFF_AH, OFF_AM, tid);
    split_to(L0, nullptr, sm, OFF_BH, OFF_BM, tid);
    __syncthreads();
    for (int u = 0; u < 8; u++) {
        cta_mm(sm, smb,
               (u < 7) ? (L0 + (size_t)(u + 1) * MATN) : nullptr,
               L0 + (size_t)u * MATN, nullptr, false, tid);
    }
}

__global__ void __launch_bounds__(256) k_xcopy(const float* __restrict__ ao,
                                               float* __restrict__ x) {
    int b = blockIdx.x, tid = threadIdx.x;
    const float* s = ao + (size_t)(b * SEQ + (SEQ - 1)) * MATN;
    float* d = x + (size_t)b * MATN;
    for (int o = tid << 2; o < MATN; o += 1024)
        *(float4*)(d + o) = *(const float4*)(s + o);
}

extern "C" void kernel_launch(void* const* d_in, const int* in_sizes, int n_in,
                              void* d_out, int out_size) {
    const float* in = (const float*)d_in[0];
    float* out = (float*)d_out;
    const size_t AO = (size_t)BSZ * SEQ * MATN;
    const size_t XN = (size_t)BSZ * MATN;

    float* x = nullptr;
    float* ao = out;
    if ((size_t)out_size >= AO + XN) { x = out; ao = out + XN; }

    cudaFuncSetAttribute(k_phase1, cudaFuncAttributeMaxDynamicSharedMemorySize, SMEM_TOTAL);
    cudaFuncSetAttribute(k_scan,   cudaFuncAttributeMaxDynamicSharedMemorySize, SMEM_TOTAL);
    cudaFuncSetAttribute(k_apply,  cudaFuncAttributeMaxDynamicSharedMemorySize, SMEM_TOTAL);

    k_phase1<<<BSZ * NCH, NT, SMEM_TOTAL>>>(in, ao);
    k_scan<<<BSZ * NCH, NT, SMEM_TOTAL>>>(1, 0);
    k_scan<<<BSZ * NCH, NT, SMEM_TOTAL>>>(2, 1);
    k_scan<<<BSZ * NCH, NT, SMEM_TOTAL>>>(4, 0);
    k_scan<<<BSZ * NCH, NT, SMEM_TOTAL>>>(8, 1);
    k_apply<<<BSZ * 15 * 2, NT, SMEM_TOTAL>>>(ao);
    if (x) k_xcopy<<<BSZ, 256>>>(ao, x);
}

// round 10
// speedup vs baseline: 2.2102x; 1.0056x over previous
#include <cuda_runtime.h>
#include <cuda_bf16.h>
#include <cstdint>

#define DD    128
#define MATN  16384
#define BSZ   32
#define SEQ   256
#define CHUNK 16
#define NCH   16

#define NT    512                 // threads per CTA (16 warps)
#define STRB  272                 // smem row stride bytes (17*16 -> conflict-free ldmatrix)
#define TERM  (128 * STRB)        // one 128x128 bf16 term tile: 34816 B
#define OFF_AH 0
#define OFF_AM TERM
#define OFF_BH (2 * TERM)
#define OFF_BM (3 * TERM)
#define OFF_ST (4 * TERM)         // raw fp32 staging for next B (65536 B)
#define SMEM_TOTAL (4 * TERM + 65536)   // 204800 B

__device__ __align__(16) float g_T0[(size_t)BSZ * NCH * MATN];
__device__ __align__(16) float g_T1[(size_t)BSZ * NCH * MATN];

// ---------------- PTX helpers ----------------
__device__ __forceinline__ uint32_t smem_u32(const void* p) {
    uint32_t a;
    asm("{ .reg .u64 t; cvta.to.shared.u64 t, %1; cvt.u32.u64 %0, t; }" : "=r"(a) : "l"(p));
    return a;
}
__device__ __forceinline__ void ldsm4(uint32_t* r, uint32_t a) {
    asm volatile("ldmatrix.sync.aligned.m8n8.x4.shared.b16 {%0,%1,%2,%3}, [%4];"
                 : "=r"(r[0]), "=r"(r[1]), "=r"(r[2]), "=r"(r[3]) : "r"(a));
}
__device__ __forceinline__ void ldsm2t(uint32_t* r, uint32_t a) {
    asm volatile("ldmatrix.sync.aligned.m8n8.x2.trans.shared.b16 {%0,%1}, [%2];"
                 : "=r"(r[0]), "=r"(r[1]) : "r"(a));
}
__device__ __forceinline__ void mma16816(float* c, const uint32_t* a, const uint32_t* b) {
    asm volatile(
        "mma.sync.aligned.m16n8k16.row.col.f32.bf16.bf16.f32 "
        "{%0,%1,%2,%3}, {%4,%5,%6,%7}, {%8,%9}, {%0,%1,%2,%3};"
        : "+f"(c[0]), "+f"(c[1]), "+f"(c[2]), "+f"(c[3])
        : "r"(a[0]), "r"(a[1]), "r"(a[2]), "r"(a[3]), "r"(b[0]), "r"(b[1]));
}
__device__ __forceinline__ void cpasync16(uint32_t dst, const void* src) {
    asm volatile("cp.async.cg.shared.global [%0], [%1], 16;" :: "r"(dst), "l"(src) : "memory");
}
__device__ __forceinline__ void cp_commit() { asm volatile("cp.async.commit_group;" ::: "memory"); }
__device__ __forceinline__ void cp_wait0()  { asm volatile("cp.async.wait_group 0;"  ::: "memory"); }

// split fp32 -> (h, m) bf16 pair
__device__ __forceinline__ void split1(float f, unsigned short& h, unsigned short& m) {
    __nv_bfloat16 bh = __float2bfloat16(f);
    float r = f - __bfloat162float(bh);
    __nv_bfloat16 bm = __float2bfloat16(r);
    h = __bfloat16_as_ushort(bh);
    m = __bfloat16_as_ushort(bm);
}
__device__ __forceinline__ void split4(float4 v, uint2& H, uint2& M) {
    unsigned short h[4], m[4];
    split1(v.x, h[0], m[0]); split1(v.y, h[1], m[1]);
    split1(v.z, h[2], m[2]); split1(v.w, h[3], m[3]);
    H.x = h[0] | ((uint32_t)h[1] << 16);  H.y = h[2] | ((uint32_t)h[3] << 16);
    M.x = m[0] | ((uint32_t)m[1] << 16);  M.y = m[2] | ((uint32_t)m[3] << 16);
}

// Split a global fp32 128x128 row-major matrix into SMEM term tiles at offH/offM.
// Optionally mirror the fp32 matrix to `mirror` (coalesced copy). NT=512 threads.
__device__ __forceinline__ void split_to(const float* __restrict__ G,
                                         float* __restrict__ mirror,
                                         char* sm, int offH, int offM, int tid) {
#pragma unroll 4
    for (int it = 0; it < 8; it++) {
        int o = (tid << 2) + (it << 11);
        float4 v = *(const float4*)(G + o);
        if (mirror) *(float4*)(mirror + o) = v;
        uint2 H, M; split4(v, H, M);
        int off = (o >> 7) * STRB + ((o & 127) << 1);
        *(uint2*)(sm + offH + off) = H;
        *(uint2*)(sm + offM + off) = M;
    }
}

// 128x128x128 matmul on tensor cores: C = A(Ah+Am) @ B(Bh+Bm), 3-product bf16
// split, fp32 accum in registers. 16 warps, each owns a 32x32 C tile.
// Fragment double buffering + pass-reordered MMAs (hh all tiles, hm all, mh all)
// so accumulator reuses are separated by 8 independent MMAs (no RAW chains).
// cp.async-prefetches nextB (raw fp32) during compute; splits it in the epilogue.
__device__ __forceinline__ void cta_mm(char* sm, uint32_t smb,
                                       const float* __restrict__ nextB,
                                       float* __restrict__ g1,
                                       float* __restrict__ g2,
                                       bool resplitA, int tid) {
    const int lane = tid & 31, w = tid >> 5;
    const int mb = (w >> 2) << 5;   // 0/32/64/96
    const int nb = (w & 3) << 5;    // 0/32/64/96

    // async prefetch of next B tile (raw fp32 -> stage)
    if (nextB) {
#pragma unroll
        for (int it = 0; it < 8; it++)
            cpasync16(smb + OFF_ST + (uint32_t)((tid << 4) + (it << 13)),
                      nextB + (tid << 2) + (it << 11));
        cp_commit();
    }

    float acc[2][4][4];
#pragma unroll
    for (int mt = 0; mt < 2; mt++)
#pragma unroll
        for (int nt = 0; nt < 4; nt++)
#pragma unroll
            for (int i = 0; i < 4; i++) acc[mt][nt][i] = 0.f;

    const uint32_t a_lane = (uint32_t)((lane & 15) * STRB + ((lane >> 4) << 4));
    const uint32_t b_lane = (uint32_t)((lane & 15) * STRB);

    uint32_t ah[2][2][4], am[2][2][4];   // [buf][mt][reg]
    uint32_t bh[2][4][2], bm[2][4][2];   // [buf][nt][reg]

    // load k0 = 0 fragments into buf 0
#pragma unroll
    for (int mt = 0; mt < 2; mt++) {
        uint32_t base = smb + (uint32_t)((mb + mt * 16) * STRB) + a_lane;
        ldsm4(ah[0][mt], base + OFF_AH);
        ldsm4(am[0][mt], base + OFF_AM);
    }
#pragma unroll
    for (int nt = 0; nt < 4; nt++) {
        uint32_t base = smb + (uint32_t)((nb + nt * 8) << 1) + b_lane;
        ldsm2t(bh[0][nt], base + OFF_BH);
        ldsm2t(bm[0][nt], base + OFF_BM);
    }

#pragma unroll
    for (int k0 = 0; k0 < 8; k0++) {
        const int cur = k0 & 1, nxt = cur ^ 1;
        if (k0 < 7) {   // prefetch k0+1 fragments before consuming k0
            const int kk = (k0 + 1) << 4;
#pragma unroll
            for (int mt = 0; mt < 2; mt++) {
                uint32_t base = smb + (uint32_t)((mb + mt * 16) * STRB + (kk << 1)) + a_lane;
                ldsm4(ah[nxt][mt], base + OFF_AH);
                ldsm4(am[nxt][mt], base + OFF_AM);
            }
#pragma unroll
            for (int nt = 0; nt < 4; nt++) {
                uint32_t base = smb + (uint32_t)(kk * STRB + ((nb + nt * 8) << 1)) + b_lane;
                ldsm2t(bh[nxt][nt], base + OFF_BH);
                ldsm2t(bm[nxt][nt], base + OFF_BM);
            }
        }
        // pass 1: hh for all 8 tiles (independent accs)
#pragma unroll
        for (int mt = 0; mt < 2; mt++)
#pragma unroll
            for (int nt = 0; nt < 4; nt++)
                mma16816(acc[mt][nt], ah[cur][mt], bh[cur][nt]);
        // pass 2: hm
#pragma unroll
        for (int mt = 0; mt < 2; mt++)
#pragma unroll
            for (int nt = 0; nt < 4; nt++)
                mma16816(acc[mt][nt], ah[cur][mt], bm[cur][nt]);
        // pass 3: mh
#pragma unroll
        for (int mt = 0; mt < 2; mt++)
#pragma unroll
            for (int nt = 0; nt < 4; nt++)
                mma16816(acc[mt][nt], am[cur][mt], bh[cur][nt]);
    }

    __syncthreads();   // all A/B smem reads done before any overwrite below
    if (nextB) cp_wait0();   // each thread waits for (and will split) its own copies

    const int r_off = lane >> 2;
    const int c_off = (lane & 3) << 1;
#pragma unroll
    for (int mt = 0; mt < 2; mt++) {
#pragma unroll
        for (int nt = 0; nt < 4; nt++) {
            int row0 = mb + mt * 16 + r_off;
            int col  = nb + nt * 8 + c_off;
#pragma unroll
            for (int half = 0; half < 2; half++) {
                int row = row0 + half * 8;
                float vx = acc[mt][nt][2 * half];
                float vy = acc[mt][nt][2 * half + 1];
                if (g1) *(float2*)(g1 + ((size_t)row << 7) + col) = make_float2(vx, vy);
                if (g2) *(float2*)(g2 + ((size_t)row << 7) + col) = make_float2(vx, vy);
                if (resplitA) {
                    unsigned short h0, m0, h1, m1;
                    split1(vx, h0, m0);
                    split1(vy, h1, m1);
                    int off = row * STRB + (col << 1);
                    *(uint32_t*)(sm + OFF_AH + off) = h0 | ((uint32_t)h1 << 16);
                    *(uint32_t*)(sm + OFF_AM + off) = m0 | ((uint32_t)m1 << 16);
                }
            }
        }
    }

    // split the staged next-B tile into the B term buffers (k-loop is done with them)
    if (nextB) {
        const float* st = (const float*)(sm + OFF_ST);
#pragma unroll 4
        for (int it = 0; it < 8; it++) {
            int o = (tid << 2) + (it << 11);
            float4 v = *(const float4*)(st + o);
            uint2 H, M; split4(v, H, M);
            int off = (o >> 7) * STRB + ((o & 127) << 1);
            *(uint2*)(sm + OFF_BH + off) = H;
            *(uint2*)(sm + OFF_BM + off) = M;
        }
    }
    __syncthreads();   // new A/B tiles visible before next step's compute
}

// ---------------- kernels ----------------

__global__ void __launch_bounds__(NT, 1) k_phase1(const float* __restrict__ in,
                                                  float* __restrict__ ao) {
    extern __shared__ char sm[];
    uint32_t smb = smem_u32(sm);
    int tid = threadIdx.x;
    int b = blockIdx.x >> 4, c = blockIdx.x & 15;
    const float* A0 = in + (size_t)(b * SEQ + c * CHUNK) * MATN;
    float* out0 = ao + (size_t)(b * SEQ + c * CHUNK) * MATN;

    split_to(A0, out0, sm, OFF_AH, OFF_AM, tid);            // prefix[0] = A0, mirrored out
    split_to(A0 + MATN, nullptr, sm, OFF_BH, OFF_BM, tid);  // first B
    __syncthreads();
    for (int s = 1; s < CHUNK; s++) {
        bool last = (s == CHUNK - 1);
        cta_mm(sm, smb,
               last ? nullptr : (A0 + (size_t)(s + 1) * MATN),
               out0 + (size_t)s * MATN,
               last ? (g_T0 + (size_t)(b * NCH + c) * MATN) : nullptr,
               !last, tid);
    }
}

__global__ void __launch_bounds__(NT, 1) k_scan(int dlev, int dir) {
    float* src = dir ? g_T1 : g_T0;
    float* dst = dir ? g_T0 : g_T1;
    int b = blockIdx.x >> 4, c = blockIdx.x & 15;
    int tid = threadIdx.x;
    size_t idx = (size_t)(b * NCH + c) * MATN;
    if (c < dlev) {
        for (int o = tid << 2; o < MATN; o += (NT * 4))
            *(float4*)(dst + idx + o) = *(const float4*)(src + idx + o);
        return;
    }
    extern __shared__ char sm[];
    uint32_t smb = smem_u32(sm);
    split_to(src + (size_t)(b * NCH + (c - dlev)) * MATN, nullptr, sm, OFF_AH, OFF_AM, tid);
    split_to(src + idx, nullptr, sm, OFF_BH, OFF_BM, tid);
    __syncthreads();
    cta_mm(sm, smb, nullptr, dst + idx, nullptr, false, tid);
}

// apply + fused x-write: the CTA producing ao[b][255] also writes x[b].
__global__ void __launch_bounds__(NT, 1) k_apply(float* __restrict__ ao,
                                                 float* __restrict__ xout) {
    extern __shared__ char sm[];
    uint32_t smb = smem_u32(sm);
    int tid = threadIdx.x;
    int blk = blockIdx.x;
    int b = blk / 30;
    int rem = blk % 30;
    int c = (rem >> 1) + 1;   // chunk 1..15
    int g = rem & 1;          // half of the chunk
    int t0 = c * CHUNK + g * 8;
    float* L0 = ao + (size_t)(b * SEQ + t0) * MATN;
    bool isLastCTA = (c == 15) && (g == 1);

    split_to(g_T0 + (size_t)(b * NCH + (c - 1)) * MATN, nullptr, sm, OFF_AH, OFF_AM, tid);
    split_to(L0, nullptr, sm, OFF_BH, OFF_BM, tid);
    __syncthreads();
    for (int u = 0; u < 8; u++) {
        float* g2 = (xout && isLastCTA && u == 7) ? (xout + (size_t)b * MATN) : nullptr;
        cta_mm(sm, smb,
               (u < 7) ? (L0 + (size_t)(u + 1) * MATN) : nullptr,
               L0 + (size_t)u * MATN, g2, false, tid);
    }
}

extern "C" void kernel_launch(void* const* d_in, const int* in_sizes, int n_in,
                              void* d_out, int out_size) {
    const float* in = (const float*)d_in[0];
    float* out = (float*)d_out;
    const size_t AO = (size_t)BSZ * SEQ * MATN;
    const size_t XN = (size_t)BSZ * MATN;

    float* x = nullptr;
    float* ao = out;
    if ((size_t)out_size >= AO + XN) { x = out; ao = out + XN; }

    cudaFuncSetAttribute(k_phase1, cudaFuncAttributeMaxDynamicSharedMemorySize, SMEM_TOTAL);
    cudaFuncSetAttribute(k_scan,   cudaFuncAttributeMaxDynamicSharedMemorySize, SMEM_TOTAL);
    cudaFuncSetAttribute(k_apply,  cudaFuncAttributeMaxDynamicSharedMemorySize, SMEM_TOTAL);

    k_phase1<<<BSZ * NCH, NT, SMEM_TOTAL>>>(in, ao);
    k_scan<<<BSZ * NCH, NT, SMEM_TOTAL>>>(1, 0);
    k_scan<<<BSZ * NCH, NT, SMEM_TOTAL>>>(2, 1);
    k_scan<<<BSZ * NCH, NT, SMEM_TOTAL>>>(4, 0);
    k_scan<<<BSZ * NCH, NT, SMEM_TOTAL>>>(8, 1);
    k_apply<<<BSZ * 15 * 2, NT, SMEM_TOTAL>>>(ao, x);
}

// round 12
// speedup vs baseline: 2.5064x; 1.1340x over previous
#include <cuda_runtime.h>
#include <cuda_bf16.h>
#include <cstdint>

#define DD    128
#define MATN  16384
#define BSZ   32
#define SEQ   256
#define CHUNK 32
#define NCH   8

#define NT    512                 // threads per CTA (16 warps)
#define STRB  272                 // smem row stride bytes (17*16 -> conflict-free ldmatrix)
#define TERM  (128 * STRB)        // one 128x128 bf16 term tile: 34816 B
#define OFF_AH 0
#define OFF_AM TERM
#define OFF_BH (2 * TERM)
#define OFF_BM (3 * TERM)
#define OFF_ST (4 * TERM)         // raw fp32 staging for next B (65536 B)
#define SMEM_TOTAL (4 * TERM + 65536)   // 204800 B

__device__ __align__(16) float g_T0[(size_t)BSZ * NCH * MATN];
__device__ __align__(16) float g_T1[(size_t)BSZ * NCH * MATN];

// ---------------- PTX helpers ----------------
__device__ __forceinline__ uint32_t smem_u32(const void* p) {
    uint32_t a;
    asm("{ .reg .u64 t; cvta.to.shared.u64 t, %1; cvt.u32.u64 %0, t; }" : "=r"(a) : "l"(p));
    return a;
}
__device__ __forceinline__ void ldsm4(uint32_t* r, uint32_t a) {
    asm volatile("ldmatrix.sync.aligned.m8n8.x4.shared.b16 {%0,%1,%2,%3}, [%4];"
                 : "=r"(r[0]), "=r"(r[1]), "=r"(r[2]), "=r"(r[3]) : "r"(a));
}
__device__ __forceinline__ void ldsm4t(uint32_t* r, uint32_t a) {
    asm volatile("ldmatrix.sync.aligned.m8n8.x4.trans.shared.b16 {%0,%1,%2,%3}, [%4];"
                 : "=r"(r[0]), "=r"(r[1]), "=r"(r[2]), "=r"(r[3]) : "r"(a));
}
__device__ __forceinline__ void mma16816(float* c, const uint32_t* a, const uint32_t* b) {
    asm volatile(
        "mma.sync.aligned.m16n8k16.row.col.f32.bf16.bf16.f32 "
        "{%0,%1,%2,%3}, {%4,%5,%6,%7}, {%8,%9}, {%0,%1,%2,%3};"
        : "+f"(c[0]), "+f"(c[1]), "+f"(c[2]), "+f"(c[3])
        : "r"(a[0]), "r"(a[1]), "r"(a[2]), "r"(a[3]), "r"(b[0]), "r"(b[1]));
}
__device__ __forceinline__ void cpasync16(uint32_t dst, const void* src) {
    asm volatile("cp.async.cg.shared.global [%0], [%1], 16;" :: "r"(dst), "l"(src) : "memory");
}
__device__ __forceinline__ void cp_commit() { asm volatile("cp.async.commit_group;" ::: "memory"); }
__device__ __forceinline__ void cp_wait0()  { asm volatile("cp.async.wait_group 0;"  ::: "memory"); }

// split fp32 -> (h, m) bf16 pair
__device__ __forceinline__ void split1(float f, unsigned short& h, unsigned short& m) {
    __nv_bfloat16 bh = __float2bfloat16(f);
    float r = f - __bfloat162float(bh);
    __nv_bfloat16 bm = __float2bfloat16(r);
    h = __bfloat16_as_ushort(bh);
    m = __bfloat16_as_ushort(bm);
}
__device__ __forceinline__ void split4(float4 v, uint2& H, uint2& M) {
    unsigned short h[4], m[4];
    split1(v.x, h[0], m[0]); split1(v.y, h[1], m[1]);
    split1(v.z, h[2], m[2]); split1(v.w, h[3], m[3]);
    H.x = h[0] | ((uint32_t)h[1] << 16);  H.y = h[2] | ((uint32_t)h[3] << 16);
    M.x = m[0] | ((uint32_t)m[1] << 16);  M.y = m[2] | ((uint32_t)m[3] << 16);
}

// Split a global fp32 128x128 row-major matrix into SMEM term tiles at offH/offM.
// Optionally mirror the fp32 matrix to `mirror` (coalesced copy). NT=512 threads.
__device__ __forceinline__ void split_to(const float* __restrict__ G,
                                         float* __restrict__ mirror,
                                         char* sm, int offH, int offM, int tid) {
#pragma unroll 4
    for (int it = 0; it < 8; it++) {
        int o = (tid << 2) + (it << 11);
        float4 v = *(const float4*)(G + o);
        if (mirror) *(float4*)(mirror + o) = v;
        uint2 H, M; split4(v, H, M);
        int off = (o >> 7) * STRB + ((o & 127) << 1);
        *(uint2*)(sm + offH + off) = H;
        *(uint2*)(sm + offM + off) = M;
    }
}

// 128x128x128 matmul on tensor cores: C = A(Ah+Am) @ B(Bh+Bm), 3-product bf16
// split, fp32 accum in registers. 16 warps, each owns a 32x32 C tile.
// Fragment double buffering; B fragments loaded pairwise via ldmatrix.x4.trans
// (half the LDSM count). Pass-reordered MMAs (hh, hm, mh across all tiles).
// cp.async-prefetches nextB (raw fp32) during compute; splits it in the epilogue.
__device__ __forceinline__ void cta_mm(char* sm, uint32_t smb,
                                       const float* __restrict__ nextB,
                                       float* __restrict__ g1,
                                       float* __restrict__ g2,
                                       bool resplitA, int tid) {
    const int lane = tid & 31, w = tid >> 5;
    const int mb = (w >> 2) << 5;   // 0/32/64/96
    const int nb = (w & 3) << 5;    // 0/32/64/96

    // async prefetch of next B tile (raw fp32 -> stage)
    if (nextB) {
#pragma unroll
        for (int it = 0; it < 8; it++)
            cpasync16(smb + OFF_ST + (uint32_t)((tid << 4) + (it << 13)),
                      nextB + (tid << 2) + (it << 11));
        cp_commit();
    }

    float acc[2][4][4];
#pragma unroll
    for (int mt = 0; mt < 2; mt++)
#pragma unroll
        for (int nt = 0; nt < 4; nt++)
#pragma unroll
            for (int i = 0; i < 4; i++) acc[mt][nt][i] = 0.f;

    // shared lane pattern: (lane&15) rows, upper half -> +16B (8 cols / 16B row chunk)
    const uint32_t q_lane = (uint32_t)((lane & 15) * STRB + ((lane >> 4) << 4));

    uint32_t ah[2][2][4], am[2][2][4];   // [buf][mt][reg]
    uint32_t bh[2][2][4], bm[2][2][4];   // [buf][pair][reg] pair p covers nt=2p,2p+1

    // load k0 = 0 fragments into buf 0
#pragma unroll
    for (int mt = 0; mt < 2; mt++) {
        uint32_t base = smb + (uint32_t)((mb + mt * 16) * STRB) + q_lane;
        ldsm4(ah[0][mt], base + OFF_AH);
        ldsm4(am[0][mt], base + OFF_AM);
    }
#pragma unroll
    for (int p = 0; p < 2; p++) {
        uint32_t base = smb + (uint32_t)((nb + p * 16) << 1) + q_lane;
        ldsm4t(bh[0][p], base + OFF_BH);
        ldsm4t(bm[0][p], base + OFF_BM);
    }

#pragma unroll
    for (int k0 = 0; k0 < 8; k0++) {
        const int cur = k0 & 1, nxt = cur ^ 1;
        if (k0 < 7) {   // prefetch k0+1 fragments before consuming k0
            const int kk = (k0 + 1) << 4;
#pragma unroll
            for (int mt = 0; mt < 2; mt++) {
                uint32_t base = smb + (uint32_t)((mb + mt * 16) * STRB + (kk << 1)) + q_lane;
                ldsm4(ah[nxt][mt], base + OFF_AH);
                ldsm4(am[nxt][mt], base + OFF_AM);
            }
#pragma unroll
            for (int p = 0; p < 2; p++) {
                uint32_t base = smb + (uint32_t)(kk * STRB + ((nb + p * 16) << 1)) + q_lane;
                ldsm4t(bh[nxt][p], base + OFF_BH);
                ldsm4t(bm[nxt][p], base + OFF_BM);
            }
        }
        // pass 1: hh (independent accs)
#pragma unroll
        for (int mt = 0; mt < 2; mt++)
#pragma unroll
            for (int nt = 0; nt < 4; nt++)
                mma16816(acc[mt][nt], ah[cur][mt], &bh[cur][nt >> 1][(nt & 1) << 1]);
        // pass 2: hm
#pragma unroll
        for (int mt = 0; mt < 2; mt++)
#pragma unroll
            for (int nt = 0; nt < 4; nt++)
                mma16816(acc[mt][nt], ah[cur][mt], &bm[cur][nt >> 1][(nt & 1) << 1]);
        // pass 3: mh
#pragma unroll
        for (int mt = 0; mt < 2; mt++)
#pragma unroll
            for (int nt = 0; nt < 4; nt++)
                mma16816(acc[mt][nt], am[cur][mt], &bh[cur][nt >> 1][(nt & 1) << 1]);
    }

    __syncthreads();   // all A/B smem reads done before any overwrite below
    if (nextB) cp_wait0();   // each thread waits for (and will split) its own copies

    const int r_off = lane >> 2;
    const int c_off = (lane & 3) << 1;
#pragma unroll
    for (int mt = 0; mt < 2; mt++) {
#pragma unroll
        for (int nt = 0; nt < 4; nt++) {
            int row0 = mb + mt * 16 + r_off;
            int col  = nb + nt * 8 + c_off;
#pragma unroll
            for (int half = 0; half < 2; half++) {
                int row = row0 + half * 8;
                float vx = acc[mt][nt][2 * half];
                float vy = acc[mt][nt][2 * half + 1];
                if (g1) *(float2*)(g1 + ((size_t)row << 7) + col) = make_float2(vx, vy);
                if (g2) *(float2*)(g2 + ((size_t)row << 7) + col) = make_float2(vx, vy);
                if (resplitA) {
                    unsigned short h0, m0, h1, m1;
                    split1(vx, h0, m0);
                    split1(vy, h1, m1);
                    int off = row * STRB + (col << 1);
                    *(uint32_t*)(sm + OFF_AH + off) = h0 | ((uint32_t)h1 << 16);
                    *(uint32_t*)(sm + OFF_AM + off) = m0 | ((uint32_t)m1 << 16);
                }
            }
        }
    }

    // split the staged next-B tile into the B term buffers (k-loop is done with them)
    if (nextB) {
        const float* st = (const float*)(sm + OFF_ST);
#pragma unroll 4
        for (int it = 0; it < 8; it++) {
            int o = (tid << 2) + (it << 11);
            float4 v = *(const float4*)(st + o);
            uint2 H, M; split4(v, H, M);
            int off = (o >> 7) * STRB + ((o & 127) << 1);
            *(uint2*)(sm + OFF_BH + off) = H;
            *(uint2*)(sm + OFF_BM + off) = M;
        }
    }
    __syncthreads();   // new A/B tiles visible before next step's compute
}

// ---------------- kernels ----------------

__global__ void __launch_bounds__(NT, 1) k_phase1(const float* __restrict__ in,
                                                  float* __restrict__ ao) {
    extern __shared__ char sm[];
    uint32_t smb = smem_u32(sm);
    int tid = threadIdx.x;
    int b = blockIdx.x >> 3, c = blockIdx.x & 7;
    const float* A0 = in + (size_t)(b * SEQ + c * CHUNK) * MATN;
    float* out0 = ao + (size_t)(b * SEQ + c * CHUNK) * MATN;

    split_to(A0, out0, sm, OFF_AH, OFF_AM, tid);            // prefix[0] = A0, mirrored out
    split_to(A0 + MATN, nullptr, sm, OFF_BH, OFF_BM, tid);  // first B
    __syncthreads();
    for (int s = 1; s < CHUNK; s++) {
        bool last = (s == CHUNK - 1);
        cta_mm(sm, smb,
               last ? nullptr : (A0 + (size_t)(s + 1) * MATN),
               out0 + (size_t)s * MATN,
               last ? (g_T0 + (size_t)(b * NCH + c) * MATN) : nullptr,
               !last, tid);
    }
}

__global__ void __launch_bounds__(NT, 1) k_scan(int dlev, int dir) {
    float* src = dir ? g_T1 : g_T0;
    float* dst = dir ? g_T0 : g_T1;
    int b = blockIdx.x >> 3, c = blockIdx.x & 7;
    int tid = threadIdx.x;
    size_t idx = (size_t)(b * NCH + c) * MATN;
    if (c < dlev) {
        for (int o = tid << 2; o < MATN; o += (NT * 4))
            *(float4*)(dst + idx + o) = *(const float4*)(src + idx + o);
        return;
    }
    extern __shared__ char sm[];
    uint32_t smb = smem_u32(sm);
    split_to(src + (size_t)(b * NCH + (c - dlev)) * MATN, nullptr, sm, OFF_AH, OFF_AM, tid);
    split_to(src + idx, nullptr, sm, OFF_BH, OFF_BM, tid);
    __syncthreads();
    cta_mm(sm, smb, nullptr, dst + idx, nullptr, false, tid);
}

// apply + fused x-write. Scan result (3 levels T0->T1->T0->T1) lives in g_T1.
__global__ void __launch_bounds__(NT, 1) k_apply(float* __restrict__ ao,
                                                 float* __restrict__ xout) {
    extern __shared__ char sm[];
    uint32_t smb = smem_u32(sm);
    int tid = threadIdx.x;
    int blk = blockIdx.x;
    int b = blk / 28;
    int rem = blk % 28;
    int c = (rem >> 2) + 1;   // chunk 1..7
    int q = rem & 3;          // quarter of the chunk (8 matmuls each)
    int t0 = c * CHUNK + q * 8;
    float* L0 = ao + (size_t)(b * SEQ + t0) * MATN;
    bool isLastCTA = (c == NCH - 1) && (q == 3);

    split_to(g_T1 + (size_t)(b * NCH + (c - 1)) * MATN, nullptr, sm, OFF_AH, OFF_AM, tid);
    split_to(L0, nullptr, sm, OFF_BH, OFF_BM, tid);
    __syncthreads();
    for (int u = 0; u < 8; u++) {
        float* g2 = (xout && isLastCTA && u == 7) ? (xout + (size_t)b * MATN) : nullptr;
        cta_mm(sm, smb,
               (u < 7) ? (L0 + (size_t)(u + 1) * MATN) : nullptr,
               L0 + (size_t)u * MATN, g2, false, tid);
    }
}

extern "C" void kernel_launch(void* const* d_in, const int* in_sizes, int n_in,
                              void* d_out, int out_size) {
    const float* in = (const float*)d_in[0];
    float* out = (float*)d_out;
    const size_t AO = (size_t)BSZ * SEQ * MATN;
    const size_t XN = (size_t)BSZ * MATN;

    float* x = nullptr;
    float* ao = out;
    if ((size_t)out_size >= AO + XN) { x = out; ao = out + XN; }

    cudaFuncSetAttribute(k_phase1, cudaFuncAttributeMaxDynamicSharedMemorySize, SMEM_TOTAL);
    cudaFuncSetAttribute(k_scan,   cudaFuncAttributeMaxDynamicSharedMemorySize, SMEM_TOTAL);
    cudaFuncSetAttribute(k_apply,  cudaFuncAttributeMaxDynamicSharedMemorySize, SMEM_TOTAL);

    k_phase1<<<BSZ * NCH, NT, SMEM_TOTAL>>>(in, ao);
    k_scan<<<BSZ * NCH, NT, SMEM_TOTAL>>>(1, 0);   // T0 -> T1
    k_scan<<<BSZ * NCH, NT, SMEM_TOTAL>>>(2, 1);   // T1 -> T0
    k_scan<<<BSZ * NCH, NT, SMEM_TOTAL>>>(4, 0);   // T0 -> T1 (final in T1)
    k_apply<<<BSZ * 7 * 4, NT, SMEM_TOTAL>>>(ao, x);
}

// round 14
// speedup vs baseline: 2.9566x; 1.1796x over previous
#include <cuda_runtime.h>
#include <cuda_bf16.h>
#include <cstdint>

#define DD    128
#define MATN  16384
#define BSZ   32
#define SEQ   256
#define CHUNK 64
#define NCH   4

#define NT    512                 // threads per CTA (16 warps)
#define STRB  272                 // smem row stride bytes (17*16 -> conflict-free ldmatrix)
#define TERM  (128 * STRB)        // one 128x128 bf16 term tile: 34816 B
#define OFF_AH 0
#define OFF_AM TERM
#define OFF_BH (2 * TERM)
#define OFF_BM (3 * TERM)
#define OFF_ST (4 * TERM)         // raw fp32 staging for next B (65536 B)
#define SMEM_TOTAL (4 * TERM + 65536)   // 204800 B

__device__ __align__(16) float g_T0[(size_t)BSZ * NCH * MATN];
__device__ __align__(16) float g_T1[(size_t)BSZ * NCH * MATN];

// ---------------- PTX helpers ----------------
__device__ __forceinline__ uint32_t smem_u32(const void* p) {
    uint32_t a;
    asm("{ .reg .u64 t; cvta.to.shared.u64 t, %1; cvt.u32.u64 %0, t; }" : "=r"(a) : "l"(p));
    return a;
}
__device__ __forceinline__ void ldsm4(uint32_t* r, uint32_t a) {
    asm volatile("ldmatrix.sync.aligned.m8n8.x4.shared.b16 {%0,%1,%2,%3}, [%4];"
                 : "=r"(r[0]), "=r"(r[1]), "=r"(r[2]), "=r"(r[3]) : "r"(a));
}
__device__ __forceinline__ void ldsm4t(uint32_t* r, uint32_t a) {
    asm volatile("ldmatrix.sync.aligned.m8n8.x4.trans.shared.b16 {%0,%1,%2,%3}, [%4];"
                 : "=r"(r[0]), "=r"(r[1]), "=r"(r[2]), "=r"(r[3]) : "r"(a));
}
__device__ __forceinline__ void mma16816(float* c, const uint32_t* a, const uint32_t* b) {
    asm volatile(
        "mma.sync.aligned.m16n8k16.row.col.f32.bf16.bf16.f32 "
        "{%0,%1,%2,%3}, {%4,%5,%6,%7}, {%8,%9}, {%0,%1,%2,%3};"
        : "+f"(c[0]), "+f"(c[1]), "+f"(c[2]), "+f"(c[3])
        : "r"(a[0]), "r"(a[1]), "r"(a[2]), "r"(a[3]), "r"(b[0]), "r"(b[1]));
}
__device__ __forceinline__ void cpasync16(uint32_t dst, const void* src) {
    asm volatile("cp.async.cg.shared.global [%0], [%1], 16;" :: "r"(dst), "l"(src) : "memory");
}
__device__ __forceinline__ void cp_commit() { asm volatile("cp.async.commit_group;" ::: "memory"); }
__device__ __forceinline__ void cp_wait0()  { asm volatile("cp.async.wait_group 0;"  ::: "memory"); }

// packed split: two fp32 -> packed bf16x2 high word + packed bf16x2 mid word.
// cvt.rn matches __float2bfloat16 rounding; float(h) is a pure 16-bit shift.
__device__ __forceinline__ void splitpair(float f0, float f1, uint32_t& H, uint32_t& M) {
    asm("cvt.rn.bf16x2.f32 %0, %1, %2;" : "=r"(H) : "f"(f1), "f"(f0));
    float fh0 = __uint_as_float(H << 16);
    float fh1 = __uint_as_float(H & 0xffff0000u);
    float r0 = f0 - fh0;
    float r1 = f1 - fh1;
    asm("cvt.rn.bf16x2.f32 %0, %1, %2;" : "=r"(M) : "f"(r1), "f"(r0));
}
__device__ __forceinline__ void split4(float4 v, uint2& H, uint2& M) {
    splitpair(v.x, v.y, H.x, M.x);
    splitpair(v.z, v.w, H.y, M.y);
}

// Split a global fp32 128x128 row-major matrix into SMEM term tiles at offH/offM.
// Optionally mirror the fp32 matrix to `mirror` (coalesced copy). NT=512 threads.
__device__ __forceinline__ void split_to(const float* __restrict__ G,
                                         float* __restrict__ mirror,
                                         char* sm, int offH, int offM, int tid) {
#pragma unroll 4
    for (int it = 0; it < 8; it++) {
        int o = (tid << 2) + (it << 11);
        float4 v = *(const float4*)(G + o);
        if (mirror) *(float4*)(mirror + o) = v;
        uint2 H, M; split4(v, H, M);
        int off = (o >> 7) * STRB + ((o & 127) << 1);
        *(uint2*)(sm + offH + off) = H;
        *(uint2*)(sm + offM + off) = M;
    }
}

// 128x128x128 matmul on tensor cores: C = A(Ah+Am) @ B(Bh+Bm), 3-product bf16
// split, fp32 accum in registers. 16 warps, each owns a 32x32 C tile.
// Fragment double buffering; B fragments loaded pairwise via ldmatrix.x4.trans.
// Pass-reordered MMAs (hh, hm, mh across all tiles). cp.async-prefetches nextB
// (raw fp32) during compute; splits it in the epilogue.
__device__ __forceinline__ void cta_mm(char* sm, uint32_t smb,
                                       const float* __restrict__ nextB,
                                       float* __restrict__ g1,
                                       float* __restrict__ g2,
                                       bool resplitA, int tid) {
    const int lane = tid & 31, w = tid >> 5;
    const int mb = (w >> 2) << 5;   // 0/32/64/96
    const int nb = (w & 3) << 5;    // 0/32/64/96

    // async prefetch of next B tile (raw fp32 -> stage)
    if (nextB) {
#pragma unroll
        for (int it = 0; it < 8; it++)
            cpasync16(smb + OFF_ST + (uint32_t)((tid << 4) + (it << 13)),
                      nextB + (tid << 2) + (it << 11));
        cp_commit();
    }

    float acc[2][4][4];
#pragma unroll
    for (int mt = 0; mt < 2; mt++)
#pragma unroll
        for (int nt = 0; nt < 4; nt++)
#pragma unroll
            for (int i = 0; i < 4; i++) acc[mt][nt][i] = 0.f;

    // shared lane pattern: (lane&15) rows, upper half -> +16B (8 cols / 16B row chunk)
    const uint32_t q_lane = (uint32_t)((lane & 15) * STRB + ((lane >> 4) << 4));

    uint32_t ah[2][2][4], am[2][2][4];   // [buf][mt][reg]
    uint32_t bh[2][2][4], bm[2][2][4];   // [buf][pair][reg] pair p covers nt=2p,2p+1

    // load k0 = 0 fragments into buf 0
#pragma unroll
    for (int mt = 0; mt < 2; mt++) {
        uint32_t base = smb + (uint32_t)((mb + mt * 16) * STRB) + q_lane;
        ldsm4(ah[0][mt], base + OFF_AH);
        ldsm4(am[0][mt], base + OFF_AM);
    }
#pragma unroll
    for (int p = 0; p < 2; p++) {
        uint32_t base = smb + (uint32_t)((nb + p * 16) << 1) + q_lane;
        ldsm4t(bh[0][p], base + OFF_BH);
        ldsm4t(bm[0][p], base + OFF_BM);
    }

#pragma unroll
    for (int k0 = 0; k0 < 8; k0++) {
        const int cur = k0 & 1, nxt = cur ^ 1;
        if (k0 < 7) {   // prefetch k0+1 fragments before consuming k0
            const int kk = (k0 + 1) << 4;
#pragma unroll
            for (int mt = 0; mt < 2; mt++) {
                uint32_t base = smb + (uint32_t)((mb + mt * 16) * STRB + (kk << 1)) + q_lane;
                ldsm4(ah[nxt][mt], base + OFF_AH);
                ldsm4(am[nxt][mt], base + OFF_AM);
            }
#pragma unroll
            for (int p = 0; p < 2; p++) {
                uint32_t base = smb + (uint32_t)(kk * STRB + ((nb + p * 16) << 1)) + q_lane;
                ldsm4t(bh[nxt][p], base + OFF_BH);
                ldsm4t(bm[nxt][p], base + OFF_BM);
            }
        }
        // pass 1: hh (independent accs)
#pragma unroll
        for (int mt = 0; mt < 2; mt++)
#pragma unroll
            for (int nt = 0; nt < 4; nt++)
                mma16816(acc[mt][nt], ah[cur][mt], &bh[cur][nt >> 1][(nt & 1) << 1]);
        // pass 2: hm
#pragma unroll
        for (int mt = 0; mt < 2; mt++)
#pragma unroll
            for (int nt = 0; nt < 4; nt++)
                mma16816(acc[mt][nt], ah[cur][mt], &bm[cur][nt >> 1][(nt & 1) << 1]);
        // pass 3: mh
#pragma unroll
        for (int mt = 0; mt < 2; mt++)
#pragma unroll
            for (int nt = 0; nt < 4; nt++)
                mma16816(acc[mt][nt], am[cur][mt], &bh[cur][nt >> 1][(nt & 1) << 1]);
    }

    __syncthreads();   // all A/B smem reads done before any overwrite below
    if (nextB) cp_wait0();   // each thread waits for (and will split) its own copies

    const int r_off = lane >> 2;
    const int c_off = (lane & 3) << 1;
#pragma unroll
    for (int mt = 0; mt < 2; mt++) {
#pragma unroll
        for (int nt = 0; nt < 4; nt++) {
            int row0 = mb + mt * 16 + r_off;
            int col  = nb + nt * 8 + c_off;
#pragma unroll
            for (int half = 0; half < 2; half++) {
                int row = row0 + half * 8;
                float vx = acc[mt][nt][2 * half];
                float vy = acc[mt][nt][2 * half + 1];
                if (g1) *(float2*)(g1 + ((size_t)row << 7) + col) = make_float2(vx, vy);
                if (g2) *(float2*)(g2 + ((size_t)row << 7) + col) = make_float2(vx, vy);
                if (resplitA) {
                    uint32_t Hw, Mw;
                    splitpair(vx, vy, Hw, Mw);   // packed h0|h1<<16 directly
                    int off = row * STRB + (col << 1);
                    *(uint32_t*)(sm + OFF_AH + off) = Hw;
                    *(uint32_t*)(sm + OFF_AM + off) = Mw;
                }
            }
        }
    }

    // split the staged next-B tile into the B term buffers (k-loop is done with them)
    if (nextB) {
        const float* st = (const float*)(sm + OFF_ST);
#pragma unroll 4
        for (int it = 0; it < 8; it++) {
            int o = (tid << 2) + (it << 11);
            float4 v = *(const float4*)(st + o);
            uint2 H, M; split4(v, H, M);
            int off = (o >> 7) * STRB + ((o & 127) << 1);
            *(uint2*)(sm + OFF_BH + off) = H;
            *(uint2*)(sm + OFF_BM + off) = M;
        }
    }
    __syncthreads();   // new A/B tiles visible before next step's compute
}

// ---------------- kernels ----------------

__global__ void __launch_bounds__(NT, 1) k_phase1(const float* __restrict__ in,
                                                  float* __restrict__ ao) {
    extern __shared__ char sm[];
    uint32_t smb = smem_u32(sm);
    int tid = threadIdx.x;
    int b = blockIdx.x >> 2, c = blockIdx.x & 3;
    const float* A0 = in + (size_t)(b * SEQ + c * CHUNK) * MATN;
    float* out0 = ao + (size_t)(b * SEQ + c * CHUNK) * MATN;

    split_to(A0, out0, sm, OFF_AH, OFF_AM, tid);            // prefix[0] = A0, mirrored out
    split_to(A0 + MATN, nullptr, sm, OFF_BH, OFF_BM, tid);  // first B
    __syncthreads();
    for (int s = 1; s < CHUNK; s++) {
        bool last = (s == CHUNK - 1);
        cta_mm(sm, smb,
               last ? nullptr : (A0 + (size_t)(s + 1) * MATN),
               out0 + (size_t)s * MATN,
               last ? (g_T0 + (size_t)(b * NCH + c) * MATN) : nullptr,
               !last, tid);
    }
}

__global__ void __launch_bounds__(NT, 1) k_scan(int dlev, int dir) {
    float* src = dir ? g_T1 : g_T0;
    float* dst = dir ? g_T0 : g_T1;
    int b = blockIdx.x >> 2, c = blockIdx.x & 3;
    int tid = threadIdx.x;
    size_t idx = (size_t)(b * NCH + c) * MATN;
    if (c < dlev) {
        for (int o = tid << 2; o < MATN; o += (NT * 4))
            *(float4*)(dst + idx + o) = *(const float4*)(src + idx + o);
        return;
    }
    extern __shared__ char sm[];
    uint32_t smb = smem_u32(sm);
    split_to(src + (size_t)(b * NCH + (c - dlev)) * MATN, nullptr, sm, OFF_AH, OFF_AM, tid);
    split_to(src + idx, nullptr, sm, OFF_BH, OFF_BM, tid);
    __syncthreads();
    cta_mm(sm, smb, nullptr, dst + idx, nullptr, false, tid);
}

// apply + fused x-write. Scan result (2 levels: T0->T1->T0) lives in g_T0.
__global__ void __launch_bounds__(NT, 1) k_apply(float* __restrict__ ao,
                                                 float* __restrict__ xout) {
    extern __shared__ char sm[];
    uint32_t smb = smem_u32(sm);
    int tid = threadIdx.x;
    int blk = blockIdx.x;
    int b = blk / 24;
    int rem = blk % 24;
    int c = (rem >> 3) + 1;   // chunk 1..3
    int q = rem & 7;          // eighth of the chunk (8 matmuls each)
    int t0 = c * CHUNK + q * 8;
    float* L0 = ao + (size_t)(b * SEQ + t0) * MATN;
    bool isLastCTA = (c == NCH - 1) && (q == 7);

    split_to(g_T0 + (size_t)(b * NCH + (c - 1)) * MATN, nullptr, sm, OFF_AH, OFF_AM, tid);
    split_to(L0, nullptr, sm, OFF_BH, OFF_BM, tid);
    __syncthreads();
    for (int u = 0; u < 8; u++) {
        float* g2 = (xout && isLastCTA && u == 7) ? (xout + (size_t)b * MATN) : nullptr;
        cta_mm(sm, smb,
               (u < 7) ? (L0 + (size_t)(u + 1) * MATN) : nullptr,
               L0 + (size_t)u * MATN, g2, false, tid);
    }
}

extern "C" void kernel_launch(void* const* d_in, const int* in_sizes, int n_in,
                              void* d_out, int out_size) {
    const float* in = (const float*)d_in[0];
    float* out = (float*)d_out;
    const size_t AO = (size_t)BSZ * SEQ * MATN;
    const size_t XN = (size_t)BSZ * MATN;

    float* x = nullptr;
    float* ao = out;
    if ((size_t)out_size >= AO + XN) { x = out; ao = out + XN; }

    cudaFuncSetAttribute(k_phase1, cudaFuncAttributeMaxDynamicSharedMemorySize, SMEM_TOTAL);
    cudaFuncSetAttribute(k_scan,   cudaFuncAttributeMaxDynamicSharedMemorySize, SMEM_TOTAL);
    cudaFuncSetAttribute(k_apply,  cudaFuncAttributeMaxDynamicSharedMemorySize, SMEM_TOTAL);

    k_phase1<<<BSZ * NCH, NT, SMEM_TOTAL>>>(in, ao);
    k_scan<<<BSZ * NCH, NT, SMEM_TOTAL>>>(1, 0);   // T0 -> T1
    k_scan<<<BSZ * NCH, NT, SMEM_TOTAL>>>(2, 1);   // T1 -> T0 (final in T0)
    k_apply<<<BSZ * 3 * 8, NT, SMEM_TOTAL>>>(ao, x);
}